// round 8
// baseline (speedup 1.0000x reference)
#include <cuda_runtime.h>
#include <cuda_bf16.h>
#include <math.h>
#include <stdint.h>

// Problem constants
#define H_HEADS 25
#define B_DIM   8
#define N_TOK   1025
#define C_DIM   3200
#define D_HEAD  128
#define M_ROWS  (B_DIM * N_TOK)   // 8200

// Scratch (device globals: allocation inside kernel_launch is forbidden)
__device__ float g_qkv[(size_t)M_ROWS * 3 * C_DIM];               // [8200, 9600]
__device__ float g_att[(size_t)M_ROWS * C_DIM];                   // [8200, 3200]
__device__ float g_x[(size_t)M_ROWS * C_DIM];                     // rounded copy of x
__device__ float g_wqkv[(size_t)C_DIM * 3 * C_DIM];               // rounded qkv_w
__device__ float g_wproj[(size_t)C_DIM * C_DIM];                  // rounded proj_w

__device__ __forceinline__ float f_tf32(float x) {
    float r;
    asm("cvt.rna.tf32.f32 %0, %1;" : "=f"(r) : "f"(x));
    return r;
}

__device__ __forceinline__ void cp16(uint32_t dst, const void* src, int bytes) {
    asm volatile("cp.async.cg.shared.global [%0], [%1], 16, %2;\n"
                 :: "r"(dst), "l"(src), "r"(bytes));
}
__device__ __forceinline__ void cp_commit() { asm volatile("cp.async.commit_group;\n" ::); }
template<int NN>
__device__ __forceinline__ void cp_wait() { asm volatile("cp.async.wait_group %0;\n" :: "n"(NN)); }

__device__ __forceinline__ uint32_t smem_u32(const void* p) {
    return (uint32_t)__cvta_generic_to_shared(p);
}

__device__ __forceinline__ void mma_tf32(float (&d)[4], const unsigned (&a)[4], const unsigned (&b)[2]) {
    asm volatile(
        "mma.sync.aligned.m16n8k8.row.col.f32.tf32.tf32.f32 "
        "{%0,%1,%2,%3}, {%4,%5,%6,%7}, {%8,%9}, {%0,%1,%2,%3};"
        : "+f"(d[0]), "+f"(d[1]), "+f"(d[2]), "+f"(d[3])
        : "r"(a[0]), "r"(a[1]), "r"(a[2]), "r"(a[3]), "r"(b[0]), "r"(b[1]));
}

// =====================================================================
// Batched TF32 GEMM, operands PRE-ROUNDED to tf32 in gmem.
// 2-stage cp.async pipeline, 2 CTAs/SM (smem 104KB, regs capped at 128).
// Used for QKV and Proj GEMMs.
// =====================================================================
template<int BN, bool TRANS_B>
__global__ void __launch_bounds__(256, 2)
gemm_tf32(const float* __restrict__ A, const float* __restrict__ B,
          const float* __restrict__ bias, float* __restrict__ C,
          int M, int N, int K,
          long lda, long ldb, long ldc,
          float alpha, int round_out, int TM, int TN)
{
    constexpr int NFR = BN / 32;
    constexpr int AS_STRIDE = 36;
    constexpr int BS_STRIDE = TRANS_B ? 36 : (BN + 8);
    constexpr int AS_ELE = 128 * AS_STRIDE;
    constexpr int BS_ELE = TRANS_B ? BN * 36 : 32 * (BN + 8);
    constexpr int STAGES = 2;

    extern __shared__ float sm[];
    float* As = sm;
    float* Bs = sm + STAGES * AS_ELE;

    // m-grouped rasterization
    int tm, tn;
    {
        const int GM = 16;
        int per = GM * TN;
        int g = blockIdx.x / per, r = blockIdx.x - g * per;
        int rows = TM - g * GM; if (rows > GM) rows = GM;
        tm = g * GM + r % rows;
        tn = r / rows;
    }
    const int bm0 = tm * 128;
    const int bn0 = tn * BN;

    const int tid = threadIdx.x;
    const int lane = tid & 31, warp = tid >> 5;
    const int wm = warp & 1, wn = warp >> 1;
    const int lr = lane >> 2, lc = lane & 3;

    float acc[4][NFR][4];
    #pragma unroll
    for (int mi = 0; mi < 4; mi++)
        #pragma unroll
        for (int ni = 0; ni < NFR; ni++)
            #pragma unroll
            for (int r = 0; r < 4; r++)
                acc[mi][ni][r] = 0.f;

    const int T = (K + 31) / 32;

    auto load_tiles = [&](int t, int s) {
        int k0 = t * 32;
        uint32_t as_base = smem_u32(As + s * AS_ELE);
        uint32_t bs_base = smem_u32(Bs + s * BS_ELE);
        #pragma unroll
        for (int i = 0; i < 4; i++) {
            int f = tid + i * 256;
            int row = f >> 3, kq = (f & 7) * 4;
            int gm = bm0 + row, gk = k0 + kq;
            int bytes = 0;
            const float* src = A;
            if (gm < M) {
                int rem = K - gk;
                if (rem > 0) { bytes = rem >= 4 ? 16 : rem * 4; src = A + (long)gm * lda + gk; }
            }
            cp16(as_base + (uint32_t)(row * AS_STRIDE + kq) * 4u, src, bytes);
        }
        #pragma unroll
        for (int i = 0; i < BN / 32; i++) {
            int f = tid + i * 256;
            int kr = f / (BN / 4), nq = (f % (BN / 4)) * 4;
            int gk = k0 + kr, gn = bn0 + nq;
            int bytes = 0;
            const float* src = B;
            if (gk < K && gn < N) { bytes = 16; src = B + (long)gk * ldb + gn; }
            cp16(bs_base + (uint32_t)(kr * BS_STRIDE + nq) * 4u, src, bytes);
        }
    };

    load_tiles(0, 0);
    cp_commit();

    int buf = 0;
    for (int t = 0; t < T; t++) {
        cp_wait<0>();
        __syncthreads();
        if (t + 1 < T) { load_tiles(t + 1, buf ^ 1); cp_commit(); }
        const float* Asb = As + buf * AS_ELE;
        const float* Bsb = Bs + buf * BS_ELE;
        #pragma unroll
        for (int ks = 0; ks < 4; ks++) {
            unsigned af[4][4], bf[NFR][2];
            #pragma unroll
            for (int mi = 0; mi < 4; mi++) {
                const float* p = &Asb[(wm * 64 + mi * 16 + lr) * AS_STRIDE + ks * 8 + lc];
                af[mi][0] = __float_as_uint(p[0]);
                af[mi][1] = __float_as_uint(p[8 * AS_STRIDE]);
                af[mi][2] = __float_as_uint(p[4]);
                af[mi][3] = __float_as_uint(p[8 * AS_STRIDE + 4]);
            }
            #pragma unroll
            for (int ni = 0; ni < NFR; ni++) {
                const float* p = &Bsb[(ks * 8 + lc) * BS_STRIDE + wn * (BN / 4) + ni * 8 + lr];
                bf[ni][0] = __float_as_uint(p[0]);
                bf[ni][1] = __float_as_uint(p[4 * BS_STRIDE]);
            }
            #pragma unroll
            for (int mi = 0; mi < 4; mi++)
                #pragma unroll
                for (int ni = 0; ni < NFR; ni++)
                    mma_tf32(acc[mi][ni], af[mi], bf[ni]);
        }
        __syncthreads();
        buf ^= 1;
    }

    #pragma unroll
    for (int mi = 0; mi < 4; mi++) {
        #pragma unroll
        for (int ni = 0; ni < NFR; ni++) {
            int r0 = bm0 + wm * 64 + mi * 16 + lr;
            int c0 = bn0 + wn * (BN / 4) + ni * 8 + lc * 2;
            float b0 = 0.f, b1 = 0.f;
            if (bias) {
                if (c0 < N)     b0 = bias[c0];
                if (c0 + 1 < N) b1 = bias[c0 + 1];
            }
            #pragma unroll
            for (int rr = 0; rr < 2; rr++) {
                int rw = r0 + rr * 8;
                if (rw < M) {
                    float v0 = alpha * acc[mi][ni][rr * 2]     + b0;
                    float v1 = alpha * acc[mi][ni][rr * 2 + 1] + b1;
                    if (round_out) { v0 = f_tf32(v0); v1 = f_tf32(v1); }
                    if (c0 < N)     C[(long)rw * ldc + c0]     = v0;
                    if (c0 + 1 < N) C[(long)rw * ldc + c0 + 1] = v1;
                }
            }
        }
    }
}

// =====================================================================
// Fused flash attention v2 (unchanged from R6): warp grid 4 x 2 kv-split,
// register->register P via shfl, split-KV merge at end.
// =====================================================================
#define FA_QELE  (128 * 132)       // 16896
#define FA_KVELE (64 * 132)        // 8448 per K or V
#define FA_SMEM  ((FA_QELE + 2 * 2 * FA_KVELE) * 4)   // 202752 bytes
#define FA_T     17                // ceil(1025/64)

__global__ void __launch_bounds__(256, 1)
flash_attn(const float* __restrict__ qkv, float* __restrict__ Og)
{
    extern __shared__ float fs[];
    float* Qs = fs;
    const int tid = threadIdx.x, w = tid >> 5, lane = tid & 31;
    const int wr = w >> 1, wc = w & 1;
    const int lr = lane >> 2, lc = lane & 3;
    const int qt = blockIdx.x, bh = blockIdx.y;
    const int b = bh / H_HEADS, h = bh - b * H_HEADS;
    const float scale = 0.088388347648318447f;   // 1/sqrt(128)

    const float* qbase = qkv + (size_t)b * N_TOK * (3 * C_DIM) + h * D_HEAD;

    {
        uint32_t qsm = smem_u32(Qs);
        #pragma unroll
        for (int i = 0; i < 16; i++) {
            int id = tid + i * 256;
            int r = id >> 5, kc = id & 31;
            int q = qt * 128 + r;
            const float* src = qbase; int bytes = 0;
            if (q < N_TOK) { src = qbase + (size_t)q * (3 * C_DIM) + kc * 4; bytes = 16; }
            cp16(qsm + (uint32_t)(r * 132 + kc * 4) * 4u, src, bytes);
        }
    }
    auto load_kv = [&](int t, int s) {
        float* Ks = fs + FA_QELE + s * 2 * FA_KVELE;
        float* Vs = Ks + FA_KVELE;
        uint32_t ksm = smem_u32(Ks), vsm = smem_u32(Vs);
        #pragma unroll
        for (int i = 0; i < 8; i++) {
            int id = tid + i * 256;
            int r = id >> 5, kc = id & 31;
            int kv = t * 64 + r;
            const float* srck = qbase; const float* srcv = qbase; int bytes = 0;
            if (kv < N_TOK) {
                srck = qbase + (size_t)kv * (3 * C_DIM) + C_DIM + kc * 4;
                srcv = qbase + (size_t)kv * (3 * C_DIM) + 2 * C_DIM + kc * 4;
                bytes = 16;
            }
            cp16(ksm + (uint32_t)(r * 132 + kc * 4) * 4u, srck, bytes);
            cp16(vsm + (uint32_t)(r * 132 + kc * 4) * 4u, srcv, bytes);
        }
    };
    load_kv(0, 0);
    cp_commit();

    float o[2][16][4];
    #pragma unroll
    for (int mi = 0; mi < 2; mi++)
        #pragma unroll
        for (int ni = 0; ni < 16; ni++)
            #pragma unroll
            for (int r = 0; r < 4; r++) o[mi][ni][r] = 0.f;
    float mrow[4] = {-1e30f, -1e30f, -1e30f, -1e30f};
    float lrow[4] = {0.f, 0.f, 0.f, 0.f};

    for (int t = 0; t < FA_T; t++) {
        int s = t & 1;
        cp_wait<0>();
        __syncthreads();
        if (t + 1 < FA_T) load_kv(t + 1, s ^ 1);
        cp_commit();

        float* Ks = fs + FA_QELE + s * 2 * FA_KVELE;
        float* Vs = Ks + FA_KVELE;

        float sa[2][4][4];
        #pragma unroll
        for (int mi = 0; mi < 2; mi++)
            #pragma unroll
            for (int ni = 0; ni < 4; ni++)
                #pragma unroll
                for (int r = 0; r < 4; r++) sa[mi][ni][r] = 0.f;

        #pragma unroll
        for (int ks = 0; ks < 16; ks++) {
            unsigned a[2][4], bb[4][2];
            #pragma unroll
            for (int mi = 0; mi < 2; mi++) {
                const float* pa = &Qs[(wr * 32 + mi * 16 + lr) * 132 + ks * 8 + lc];
                a[mi][0] = __float_as_uint(pa[0]);
                a[mi][1] = __float_as_uint(pa[8 * 132]);
                a[mi][2] = __float_as_uint(pa[4]);
                a[mi][3] = __float_as_uint(pa[8 * 132 + 4]);
            }
            #pragma unroll
            for (int ni = 0; ni < 4; ni++) {
                const float* pb = &Ks[(wc * 32 + ni * 8 + lr) * 132 + ks * 8 + lc];
                bb[ni][0] = __float_as_uint(pb[0]);
                bb[ni][1] = __float_as_uint(pb[4]);
            }
            #pragma unroll
            for (int mi = 0; mi < 2; mi++)
                #pragma unroll
                for (int ni = 0; ni < 4; ni++)
                    mma_tf32(sa[mi][ni], a[mi], bb[ni]);
        }

        #pragma unroll
        for (int mi = 0; mi < 2; mi++)
            #pragma unroll
            for (int ni = 0; ni < 4; ni++)
                #pragma unroll
                for (int r = 0; r < 4; r++) sa[mi][ni][r] *= scale;
        if (t == FA_T - 1) {
            #pragma unroll
            for (int ni = 0; ni < 4; ni++) {
                int col = t * 64 + wc * 32 + ni * 8 + 2 * lc;
                if (col >= N_TOK) {
                    #pragma unroll
                    for (int mi = 0; mi < 2; mi++) { sa[mi][ni][0] = -1e30f; sa[mi][ni][2] = -1e30f; }
                }
                if (col + 1 >= N_TOK) {
                    #pragma unroll
                    for (int mi = 0; mi < 2; mi++) { sa[mi][ni][1] = -1e30f; sa[mi][ni][3] = -1e30f; }
                }
            }
        }

        float tm[4] = {-1e30f, -1e30f, -1e30f, -1e30f};
        #pragma unroll
        for (int mi = 0; mi < 2; mi++)
            #pragma unroll
            for (int ni = 0; ni < 4; ni++) {
                tm[mi * 2 + 0] = fmaxf(tm[mi * 2 + 0], fmaxf(sa[mi][ni][0], sa[mi][ni][1]));
                tm[mi * 2 + 1] = fmaxf(tm[mi * 2 + 1], fmaxf(sa[mi][ni][2], sa[mi][ni][3]));
            }
        #pragma unroll
        for (int j = 0; j < 4; j++) {
            tm[j] = fmaxf(tm[j], __shfl_xor_sync(0xffffffffu, tm[j], 1));
            tm[j] = fmaxf(tm[j], __shfl_xor_sync(0xffffffffu, tm[j], 2));
        }
        float fj[4];
        #pragma unroll
        for (int j = 0; j < 4; j++) {
            float mn = fmaxf(mrow[j], tm[j]);
            fj[j] = __expf(mrow[j] - mn);
            mrow[j] = mn;
        }
        float rs[4] = {0.f, 0.f, 0.f, 0.f};
        #pragma unroll
        for (int mi = 0; mi < 2; mi++)
            #pragma unroll
            for (int ni = 0; ni < 4; ni++) {
                sa[mi][ni][0] = __expf(sa[mi][ni][0] - mrow[mi * 2]);     rs[mi * 2] += sa[mi][ni][0];
                sa[mi][ni][1] = __expf(sa[mi][ni][1] - mrow[mi * 2]);     rs[mi * 2] += sa[mi][ni][1];
                sa[mi][ni][2] = __expf(sa[mi][ni][2] - mrow[mi * 2 + 1]); rs[mi * 2 + 1] += sa[mi][ni][2];
                sa[mi][ni][3] = __expf(sa[mi][ni][3] - mrow[mi * 2 + 1]); rs[mi * 2 + 1] += sa[mi][ni][3];
            }
        #pragma unroll
        for (int j = 0; j < 4; j++) {
            rs[j] += __shfl_xor_sync(0xffffffffu, rs[j], 1);
            rs[j] += __shfl_xor_sync(0xffffffffu, rs[j], 2);
            lrow[j] = lrow[j] * fj[j] + rs[j];
        }
        #pragma unroll
        for (int mi = 0; mi < 2; mi++)
            #pragma unroll
            for (int ni = 0; ni < 16; ni++) {
                o[mi][ni][0] *= fj[mi * 2];     o[mi][ni][1] *= fj[mi * 2];
                o[mi][ni][2] *= fj[mi * 2 + 1]; o[mi][ni][3] *= fj[mi * 2 + 1];
            }
        #pragma unroll
        for (int mi = 0; mi < 2; mi++)
            #pragma unroll
            for (int ni = 0; ni < 4; ni++)
                #pragma unroll
                for (int r = 0; r < 4; r++) sa[mi][ni][r] = f_tf32(sa[mi][ni][r]);

        const int src0 = lr * 4 + (lc >> 1);
        const int src1 = src0 + 2;
        const bool odd = (lc & 1);
        #pragma unroll
        for (int ks = 0; ks < 4; ks++) {
            unsigned a[2][4];
            #pragma unroll
            for (int mi = 0; mi < 2; mi++) {
                float v00 = __shfl_sync(0xffffffffu, sa[mi][ks][0], src0);
                float v01 = __shfl_sync(0xffffffffu, sa[mi][ks][1], src0);
                float v10 = __shfl_sync(0xffffffffu, sa[mi][ks][2], src0);
                float v11 = __shfl_sync(0xffffffffu, sa[mi][ks][3], src0);
                float w00 = __shfl_sync(0xffffffffu, sa[mi][ks][0], src1);
                float w01 = __shfl_sync(0xffffffffu, sa[mi][ks][1], src1);
                float w10 = __shfl_sync(0xffffffffu, sa[mi][ks][2], src1);
                float w11 = __shfl_sync(0xffffffffu, sa[mi][ks][3], src1);
                a[mi][0] = __float_as_uint(odd ? v01 : v00);
                a[mi][1] = __float_as_uint(odd ? v11 : v10);
                a[mi][2] = __float_as_uint(odd ? w01 : w00);
                a[mi][3] = __float_as_uint(odd ? w11 : w10);
            }
            #pragma unroll
            for (int ni = 0; ni < 16; ni++) {
                unsigned bb[2];
                const float* pb = &Vs[(wc * 32 + ks * 8 + lc) * 132 + ni * 8 + lr];
                bb[0] = __float_as_uint(pb[0]);
                bb[1] = __float_as_uint(pb[4 * 132]);
                mma_tf32(o[0][ni], a[0], bb);
                mma_tf32(o[1][ni], a[1], bb);
            }
        }
    }

    __syncthreads();
    if (wc == 1) {
        #pragma unroll
        for (int mi = 0; mi < 2; mi++) {
            int r0 = wr * 32 + mi * 16 + lr;
            #pragma unroll
            for (int ni = 0; ni < 16; ni++) {
                *reinterpret_cast<float2*>(&Qs[r0 * 132 + ni * 8 + 2 * lc]) =
                    make_float2(o[mi][ni][0], o[mi][ni][1]);
                *reinterpret_cast<float2*>(&Qs[(r0 + 8) * 132 + ni * 8 + 2 * lc]) =
                    make_float2(o[mi][ni][2], o[mi][ni][3]);
            }
            if (lc == 0) {
                Qs[r0 * 132 + 128] = mrow[mi * 2];
                Qs[r0 * 132 + 129] = lrow[mi * 2];
                Qs[(r0 + 8) * 132 + 128] = mrow[mi * 2 + 1];
                Qs[(r0 + 8) * 132 + 129] = lrow[mi * 2 + 1];
            }
        }
    }
    __syncthreads();
    if (wc == 0) {
        #pragma unroll
        for (int mi = 0; mi < 2; mi++) {
            #pragma unroll
            for (int half = 0; half < 2; half++) {
                int r0 = wr * 32 + mi * 16 + lr + half * 8;
                int j = mi * 2 + half;
                float m1 = Qs[r0 * 132 + 128];
                float l1 = Qs[r0 * 132 + 129];
                float mm = fmaxf(mrow[j], m1);
                float f0 = __expf(mrow[j] - mm), f1 = __expf(m1 - mm);
                float ll = lrow[j] * f0 + l1 * f1;
                float inv = 1.f / ll;
                int rg = qt * 128 + r0;
                if (rg < N_TOK) {
                    float* dst = Og + ((size_t)(b * N_TOK + rg)) * C_DIM + h * D_HEAD;
                    #pragma unroll
                    for (int ni = 0; ni < 16; ni++) {
                        float2 o1 = *reinterpret_cast<float2*>(&Qs[r0 * 132 + ni * 8 + 2 * lc]);
                        float v0 = (o[mi][ni][half * 2]     * f0 + o1.x * f1) * inv;
                        float v1 = (o[mi][ni][half * 2 + 1] * f0 + o1.y * f1) * inv;
                        *reinterpret_cast<float2*>(&dst[ni * 8 + 2 * lc]) =
                            make_float2(f_tf32(v0), f_tf32(v1));
                    }
                }
            }
        }
    }
}

// ===================== pre/post-processing kernels =====================

__global__ void round_copy(const float* __restrict__ in, float* __restrict__ out, long n4)
{
    long i = (long)blockIdx.x * blockDim.x + threadIdx.x;
    long stride = (long)gridDim.x * blockDim.x;
    for (; i < n4; i += stride) {
        float4 v = reinterpret_cast<const float4*>(in)[i];
        v.x = f_tf32(v.x); v.y = f_tf32(v.y); v.z = f_tf32(v.z); v.w = f_tf32(v.w);
        reinterpret_cast<float4*>(out)[i] = v;
    }
}

// RMSNorm over full C for q and k segments of one qkv row, in place (tf32-rounded out).
__global__ void rmsnorm_qk(float* __restrict__ qkv,
                           const float* __restrict__ qw, const float* __restrict__ kw)
{
    float* row = qkv + (size_t)blockIdx.x * (3 * C_DIM);
    int tid = threadIdx.x;
    float sq = 0.f, sk = 0.f;
    for (int i = tid * 4; i < C_DIM; i += 256 * 4) {
        float4 q = *reinterpret_cast<const float4*>(row + i);
        float4 k = *reinterpret_cast<const float4*>(row + C_DIM + i);
        sq += q.x * q.x + q.y * q.y + q.z * q.z + q.w * q.w;
        sk += k.x * k.x + k.y * k.y + k.z * k.z + k.w * k.w;
    }
    #pragma unroll
    for (int o = 16; o; o >>= 1) {
        sq += __shfl_xor_sync(0xffffffffu, sq, o);
        sk += __shfl_xor_sync(0xffffffffu, sk, o);
    }
    __shared__ float s1[8], s2[8];
    int lane = tid & 31, warp = tid >> 5;
    if (lane == 0) { s1[warp] = sq; s2[warp] = sk; }
    __syncthreads();
    if (tid == 0) {
        float a = 0.f, b = 0.f;
        #pragma unroll
        for (int w = 0; w < 8; w++) { a += s1[w]; b += s2[w]; }
        s1[0] = rsqrtf(a / C_DIM + 1e-6f);
        s2[0] = rsqrtf(b / C_DIM + 1e-6f);
    }
    __syncthreads();
    float invq = s1[0], invk = s2[0];
    for (int i = tid * 4; i < C_DIM; i += 256 * 4) {
        float4 q = *reinterpret_cast<const float4*>(row + i);
        float4 k = *reinterpret_cast<const float4*>(row + C_DIM + i);
        q.x = f_tf32(q.x * invq * qw[i]);     q.y = f_tf32(q.y * invq * qw[i + 1]);
        q.z = f_tf32(q.z * invq * qw[i + 2]); q.w = f_tf32(q.w * invq * qw[i + 3]);
        k.x = f_tf32(k.x * invk * kw[i]);     k.y = f_tf32(k.y * invk * kw[i + 1]);
        k.z = f_tf32(k.z * invk * kw[i + 2]); k.w = f_tf32(k.w * invk * kw[i + 3]);
        *reinterpret_cast<float4*>(row + i) = q;
        *reinterpret_cast<float4*>(row + C_DIM + i) = k;
    }
}

extern "C" void kernel_launch(void* const* d_in, const int* in_sizes, int n_in,
                              void* d_out, int out_size)
{
    const float* x        = (const float*)d_in[0];
    const float* qkv_w    = (const float*)d_in[1];
    const float* qkv_b    = (const float*)d_in[2];
    const float* q_norm_w = (const float*)d_in[3];
    const float* k_norm_w = (const float*)d_in[4];
    const float* proj_w   = (const float*)d_in[5];
    const float* proj_b   = (const float*)d_in[6];
    float* out = (float*)d_out;

    float *qkvp, *attp, *xp, *wqkvp, *wprojp;
    cudaGetSymbolAddress((void**)&qkvp,  g_qkv);
    cudaGetSymbolAddress((void**)&attp,  g_att);
    cudaGetSymbolAddress((void**)&xp,    g_x);
    cudaGetSymbolAddress((void**)&wqkvp, g_wqkv);
    cudaGetSymbolAddress((void**)&wprojp,g_wproj);

    const int smem_big = 2 * (128 * 36 + 32 * 264) * (int)sizeof(float);   // 104448
    cudaFuncSetAttribute(gemm_tf32<256, false>, cudaFuncAttributeMaxDynamicSharedMemorySize, smem_big);
    cudaFuncSetAttribute(flash_attn, cudaFuncAttributeMaxDynamicSharedMemorySize, FA_SMEM);

    dim3 blk(256);

    // 0. Pre-round operands once
    round_copy<<<2048, 256>>>(x, xp, (long)M_ROWS * C_DIM / 4);
    round_copy<<<2048, 256>>>(qkv_w, wqkvp, (long)C_DIM * 3 * C_DIM / 4);
    round_copy<<<2048, 256>>>(proj_w, wprojp, (long)C_DIM * C_DIM / 4);

    // 1. QKV GEMM: [8200,3200] x [3200,9600] + bias -> g_qkv (rounded out)
    {
        int TM = (M_ROWS + 127) / 128;          // 65
        int TN = (3 * C_DIM + 255) / 256;       // 38
        gemm_tf32<256, false><<<dim3(TM * TN, 1, 1), blk, smem_big>>>(
            xp, wqkvp, qkv_b, qkvp, M_ROWS, 3 * C_DIM, C_DIM,
            C_DIM, 3 * C_DIM, 3 * C_DIM, 1.0f, 1, TM, TN);
    }

    // 2. RMSNorm q,k in place (rounded out)
    rmsnorm_qk<<<M_ROWS, blk>>>(qkvp, q_norm_w, k_norm_w);

    // 3-5. Fused flash attention -> g_att (rounded out)
    flash_attn<<<dim3(9, 200), blk, FA_SMEM>>>(qkvp, attp);

    // 6. Proj GEMM: [8200,3200] x [3200,3200] + bias -> out
    {
        int TM = (M_ROWS + 127) / 128;          // 65
        int TN = (C_DIM + 255) / 256;           // 13
        gemm_tf32<256, false><<<dim3(TM * TN, 1, 1), blk, smem_big>>>(
            attp, wprojp, proj_b, out, M_ROWS, C_DIM, C_DIM,
            C_DIM, C_DIM, C_DIM, 1.0f, 0, TM, TN);
    }
}

// round 9
// speedup vs baseline: 3.9699x; 3.9699x over previous
#include <cuda_runtime.h>
#include <cuda_fp16.h>
#include <math.h>
#include <stdint.h>

// Problem constants
#define H_HEADS 25
#define B_DIM   8
#define N_TOK   1025
#define C_DIM   3200
#define D_HEAD  128
#define M_ROWS  (B_DIM * N_TOK)   // 8200

// Scratch (device globals)
__device__ float  g_qkv[(size_t)M_ROWS * 3 * C_DIM];      // [8200, 9600] fp32 (tf32-rounded)
__device__ __half g_xh[(size_t)M_ROWS * C_DIM];           // x in fp16
__device__ __half g_wqkvh[(size_t)C_DIM * 3 * C_DIM];     // qkv_w in fp16
__device__ __half g_wprojh[(size_t)C_DIM * C_DIM];        // proj_w in fp16
__device__ __half g_atth[(size_t)M_ROWS * C_DIM];         // attention out in fp16

__device__ __forceinline__ float f_tf32(float x) {
    float r;
    asm("cvt.rna.tf32.f32 %0, %1;" : "=f"(r) : "f"(x));
    return r;
}

__device__ __forceinline__ void cp16(uint32_t dst, const void* src, int bytes) {
    asm volatile("cp.async.cg.shared.global [%0], [%1], 16, %2;\n"
                 :: "r"(dst), "l"(src), "r"(bytes));
}
__device__ __forceinline__ void cp_commit() { asm volatile("cp.async.commit_group;\n" ::); }
template<int NN>
__device__ __forceinline__ void cp_wait() { asm volatile("cp.async.wait_group %0;\n" :: "n"(NN)); }

__device__ __forceinline__ uint32_t smem_u32(const void* p) {
    return (uint32_t)__cvta_generic_to_shared(p);
}

__device__ __forceinline__ void mma_tf32(float (&d)[4], const unsigned (&a)[4], const unsigned (&b)[2]) {
    asm volatile(
        "mma.sync.aligned.m16n8k8.row.col.f32.tf32.tf32.f32 "
        "{%0,%1,%2,%3}, {%4,%5,%6,%7}, {%8,%9}, {%0,%1,%2,%3};"
        : "+f"(d[0]), "+f"(d[1]), "+f"(d[2]), "+f"(d[3])
        : "r"(a[0]), "r"(a[1]), "r"(a[2]), "r"(a[3]), "r"(b[0]), "r"(b[1]));
}

__device__ __forceinline__ void mma_f16(float (&d)[4], const unsigned (&a)[4], const unsigned (&b)[2]) {
    asm volatile(
        "mma.sync.aligned.m16n8k16.row.col.f32.f16.f16.f32 "
        "{%0,%1,%2,%3}, {%4,%5,%6,%7}, {%8,%9}, {%0,%1,%2,%3};"
        : "+f"(d[0]), "+f"(d[1]), "+f"(d[2]), "+f"(d[3])
        : "r"(a[0]), "r"(a[1]), "r"(a[2]), "r"(a[3]), "r"(b[0]), "r"(b[1]));
}

#define LDSM_X4(r0, r1, r2, r3, addr) \
    asm volatile("ldmatrix.sync.aligned.m8n8.x4.shared.b16 {%0,%1,%2,%3}, [%4];" \
                 : "=r"(r0), "=r"(r1), "=r"(r2), "=r"(r3) : "r"(addr))
#define LDSM_X4_T(r0, r1, r2, r3, addr) \
    asm volatile("ldmatrix.sync.aligned.m8n8.x4.trans.shared.b16 {%0,%1,%2,%3}, [%4];" \
                 : "=r"(r0), "=r"(r1), "=r"(r2), "=r"(r3) : "r"(addr))

// =====================================================================
// FP16 GEMM: C[f32] = A[f16, MxK row-major] * B[f16, KxN row-major] + bias
// Block tile 128x256x32, 256 threads, warp tile 64x64, m16n8k16.
// A smem: [128][40] halfs (80B rows); B smem: [32][264] halfs (528B rows).
// 3-stage cp.async pipeline; ldmatrix fragment loads.
// =====================================================================
#define HG_ASH  (128 * 40)           // halfs per A stage
#define HG_BSH  (32 * 264)           // halfs per B stage
#define HG_STH  (HG_ASH + HG_BSH)    // 13568 halfs = 27136 B
#define HG_AB   (HG_ASH * 2)         // 10240 bytes
#define HG_STB  (HG_STH * 2)         // 27136 bytes
#define HG_SMEM (3 * HG_STB)         // 81408 bytes

__global__ void __launch_bounds__(256, 1)
hgemm(const __half* __restrict__ A, const __half* __restrict__ B,
      const float* __restrict__ bias, float* __restrict__ C,
      int M, int N, int K, long lda, long ldb, long ldc,
      int round_out, int TM, int TN)
{
    extern __shared__ __half hsm[];

    // m-grouped rasterization
    int tm, tn;
    {
        const int GM = 16;
        int per = GM * TN;
        int g = blockIdx.x / per, r = blockIdx.x - g * per;
        int rows = TM - g * GM; if (rows > GM) rows = GM;
        tm = g * GM + r % rows;
        tn = r / rows;
    }
    const int bm0 = tm * 128;
    const int bn0 = tn * 256;

    const int tid = threadIdx.x;
    const int lane = tid & 31, warp = tid >> 5;
    const int wm = warp & 1, wn = warp >> 1;      // 2 x 4 warp grid
    const int lr = lane >> 2, lc = lane & 3;

    const uint32_t smbase = smem_u32(hsm);
    const int j8 = lane >> 3, i8 = lane & 7;
    // per-lane ldmatrix row-address components (bytes)
    const uint32_t a_lane = (uint32_t)((wm * 64 + (j8 & 1) * 8 + i8) * 80 + (j8 >> 1) * 16);
    const uint32_t b_lane = (uint32_t)(((j8 & 1) * 8 + i8) * 528 + (wn * 64 + (j8 >> 1) * 8) * 2);

    float acc[4][8][4];
    #pragma unroll
    for (int mi = 0; mi < 4; mi++)
        #pragma unroll
        for (int ni = 0; ni < 8; ni++)
            #pragma unroll
            for (int r = 0; r < 4; r++)
                acc[mi][ni][r] = 0.f;

    const int T = K / 32;   // K divisible by 32

    auto load_tiles = [&](int t, int s) {
        int k0 = t * 32;
        uint32_t ab = smbase + (uint32_t)s * HG_STB;
        uint32_t bb = ab + HG_AB;
        // A tile: 128 rows x 32 halfs (4 x 16B chunks per row) -> 2 iters
        #pragma unroll
        for (int i = 0; i < 2; i++) {
            int f = tid + i * 256;
            int row = f >> 2, c = f & 3;
            int gm = bm0 + row;
            const __half* src = A; int bytes = 0;
            if (gm < M) { src = A + (size_t)gm * lda + k0 + c * 8; bytes = 16; }
            cp16(ab + (uint32_t)(row * 80 + c * 16), src, bytes);
        }
        // B tile: 32 rows(k) x 256 halfs (32 x 16B chunks per row) -> 4 iters
        #pragma unroll
        for (int i = 0; i < 4; i++) {
            int f = tid + i * 256;
            int kr = f >> 5, nc = f & 31;
            int gn = bn0 + nc * 8;
            const __half* src = B; int bytes = 0;
            if (gn < N) { src = B + (size_t)(k0 + kr) * ldb + gn; bytes = 16; }
            cp16(bb + (uint32_t)(kr * 528 + nc * 16), src, bytes);
        }
    };

    load_tiles(0, 0);
    cp_commit();
    if (T > 1) { load_tiles(1, 1); }
    cp_commit();

    for (int t = 0; t < T; t++) {
        if (t + 1 < T) cp_wait<1>(); else cp_wait<0>();
        __syncthreads();
        if (t + 2 < T) { load_tiles(t + 2, (t + 2) % 3); }
        cp_commit();
        uint32_t asb = smbase + (uint32_t)(t % 3) * HG_STB;
        uint32_t bsb = asb + HG_AB;
        #pragma unroll
        for (int ks = 0; ks < 2; ks++) {            // two k16 steps per tile
            unsigned af[4][4], bf[4][4];
            #pragma unroll
            for (int mi = 0; mi < 4; mi++)
                LDSM_X4(af[mi][0], af[mi][1], af[mi][2], af[mi][3],
                        asb + a_lane + (uint32_t)(mi * 1280 + ks * 32));
            #pragma unroll
            for (int nb = 0; nb < 4; nb++)
                LDSM_X4_T(bf[nb][0], bf[nb][1], bf[nb][2], bf[nb][3],
                          bsb + b_lane + (uint32_t)(nb * 32 + ks * 8448));
            #pragma unroll
            for (int mi = 0; mi < 4; mi++)
                #pragma unroll
                for (int nb = 0; nb < 4; nb++) {
                    unsigned b0[2] = { bf[nb][0], bf[nb][1] };
                    unsigned b1[2] = { bf[nb][2], bf[nb][3] };
                    mma_f16(acc[mi][nb * 2],     af[mi], b0);
                    mma_f16(acc[mi][nb * 2 + 1], af[mi], b1);
                }
        }
        // top-of-loop barrier orders stage reuse
    }

    // epilogue
    #pragma unroll
    for (int mi = 0; mi < 4; mi++) {
        #pragma unroll
        for (int ni = 0; ni < 8; ni++) {
            int r0 = bm0 + wm * 64 + mi * 16 + lr;
            int c0 = bn0 + wn * 64 + ni * 8 + lc * 2;
            float b0 = 0.f, b1 = 0.f;
            if (bias) {
                if (c0 < N)     b0 = bias[c0];
                if (c0 + 1 < N) b1 = bias[c0 + 1];
            }
            #pragma unroll
            for (int rr = 0; rr < 2; rr++) {
                int rw = r0 + rr * 8;
                if (rw < M) {
                    float v0 = acc[mi][ni][rr * 2]     + b0;
                    float v1 = acc[mi][ni][rr * 2 + 1] + b1;
                    if (round_out) { v0 = f_tf32(v0); v1 = f_tf32(v1); }
                    if (c0 < N)     C[(long)rw * ldc + c0]     = v0;
                    if (c0 + 1 < N) C[(long)rw * ldc + c0 + 1] = v1;
                }
            }
        }
    }
}

// =====================================================================
// Fused flash attention (tf32, from R6): warp grid 4 x 2 kv-split,
// register->register P via shfl, split-KV merge; epilogue emits fp16.
// =====================================================================
#define FA_QELE  (128 * 132)
#define FA_KVELE (64 * 132)
#define FA_SMEM  ((FA_QELE + 2 * 2 * FA_KVELE) * 4)   // 202752 bytes
#define FA_T     17

__global__ void __launch_bounds__(256, 1)
flash_attn(const float* __restrict__ qkv, __half* __restrict__ Og)
{
    extern __shared__ float fs[];
    float* Qs = fs;
    const int tid = threadIdx.x, w = tid >> 5, lane = tid & 31;
    const int wr = w >> 1, wc = w & 1;
    const int lr = lane >> 2, lc = lane & 3;
    const int qt = blockIdx.x, bh = blockIdx.y;
    const int b = bh / H_HEADS, h = bh - b * H_HEADS;
    const float scale = 0.088388347648318447f;

    const float* qbase = qkv + (size_t)b * N_TOK * (3 * C_DIM) + h * D_HEAD;

    {
        uint32_t qsm = smem_u32(Qs);
        #pragma unroll
        for (int i = 0; i < 16; i++) {
            int id = tid + i * 256;
            int r = id >> 5, kc = id & 31;
            int q = qt * 128 + r;
            const float* src = qbase; int bytes = 0;
            if (q < N_TOK) { src = qbase + (size_t)q * (3 * C_DIM) + kc * 4; bytes = 16; }
            cp16(qsm + (uint32_t)(r * 132 + kc * 4) * 4u, src, bytes);
        }
    }
    auto load_kv = [&](int t, int s) {
        float* Ks = fs + FA_QELE + s * 2 * FA_KVELE;
        float* Vs = Ks + FA_KVELE;
        uint32_t ksm = smem_u32(Ks), vsm = smem_u32(Vs);
        #pragma unroll
        for (int i = 0; i < 8; i++) {
            int id = tid + i * 256;
            int r = id >> 5, kc = id & 31;
            int kv = t * 64 + r;
            const float* srck = qbase; const float* srcv = qbase; int bytes = 0;
            if (kv < N_TOK) {
                srck = qbase + (size_t)kv * (3 * C_DIM) + C_DIM + kc * 4;
                srcv = qbase + (size_t)kv * (3 * C_DIM) + 2 * C_DIM + kc * 4;
                bytes = 16;
            }
            cp16(ksm + (uint32_t)(r * 132 + kc * 4) * 4u, srck, bytes);
            cp16(vsm + (uint32_t)(r * 132 + kc * 4) * 4u, srcv, bytes);
        }
    };
    load_kv(0, 0);
    cp_commit();

    float o[2][16][4];
    #pragma unroll
    for (int mi = 0; mi < 2; mi++)
        #pragma unroll
        for (int ni = 0; ni < 16; ni++)
            #pragma unroll
            for (int r = 0; r < 4; r++) o[mi][ni][r] = 0.f;
    float mrow[4] = {-1e30f, -1e30f, -1e30f, -1e30f};
    float lrow[4] = {0.f, 0.f, 0.f, 0.f};

    for (int t = 0; t < FA_T; t++) {
        int s = t & 1;
        cp_wait<0>();
        __syncthreads();
        if (t + 1 < FA_T) load_kv(t + 1, s ^ 1);
        cp_commit();

        float* Ks = fs + FA_QELE + s * 2 * FA_KVELE;
        float* Vs = Ks + FA_KVELE;

        float sa[2][4][4];
        #pragma unroll
        for (int mi = 0; mi < 2; mi++)
            #pragma unroll
            for (int ni = 0; ni < 4; ni++)
                #pragma unroll
                for (int r = 0; r < 4; r++) sa[mi][ni][r] = 0.f;

        #pragma unroll
        for (int ks = 0; ks < 16; ks++) {
            unsigned a[2][4], bb[4][2];
            #pragma unroll
            for (int mi = 0; mi < 2; mi++) {
                const float* pa = &Qs[(wr * 32 + mi * 16 + lr) * 132 + ks * 8 + lc];
                a[mi][0] = __float_as_uint(pa[0]);
                a[mi][1] = __float_as_uint(pa[8 * 132]);
                a[mi][2] = __float_as_uint(pa[4]);
                a[mi][3] = __float_as_uint(pa[8 * 132 + 4]);
            }
            #pragma unroll
            for (int ni = 0; ni < 4; ni++) {
                const float* pb = &Ks[(wc * 32 + ni * 8 + lr) * 132 + ks * 8 + lc];
                bb[ni][0] = __float_as_uint(pb[0]);
                bb[ni][1] = __float_as_uint(pb[4]);
            }
            #pragma unroll
            for (int mi = 0; mi < 2; mi++)
                #pragma unroll
                for (int ni = 0; ni < 4; ni++)
                    mma_tf32(sa[mi][ni], a[mi], bb[ni]);
        }

        #pragma unroll
        for (int mi = 0; mi < 2; mi++)
            #pragma unroll
            for (int ni = 0; ni < 4; ni++)
                #pragma unroll
                for (int r = 0; r < 4; r++) sa[mi][ni][r] *= scale;
        if (t == FA_T - 1) {
            #pragma unroll
            for (int ni = 0; ni < 4; ni++) {
                int col = t * 64 + wc * 32 + ni * 8 + 2 * lc;
                if (col >= N_TOK) {
                    #pragma unroll
                    for (int mi = 0; mi < 2; mi++) { sa[mi][ni][0] = -1e30f; sa[mi][ni][2] = -1e30f; }
                }
                if (col + 1 >= N_TOK) {
                    #pragma unroll
                    for (int mi = 0; mi < 2; mi++) { sa[mi][ni][1] = -1e30f; sa[mi][ni][3] = -1e30f; }
                }
            }
        }

        float tm[4] = {-1e30f, -1e30f, -1e30f, -1e30f};
        #pragma unroll
        for (int mi = 0; mi < 2; mi++)
            #pragma unroll
            for (int ni = 0; ni < 4; ni++) {
                tm[mi * 2 + 0] = fmaxf(tm[mi * 2 + 0], fmaxf(sa[mi][ni][0], sa[mi][ni][1]));
                tm[mi * 2 + 1] = fmaxf(tm[mi * 2 + 1], fmaxf(sa[mi][ni][2], sa[mi][ni][3]));
            }
        #pragma unroll
        for (int j = 0; j < 4; j++) {
            tm[j] = fmaxf(tm[j], __shfl_xor_sync(0xffffffffu, tm[j], 1));
            tm[j] = fmaxf(tm[j], __shfl_xor_sync(0xffffffffu, tm[j], 2));
        }
        float fj[4];
        #pragma unroll
        for (int j = 0; j < 4; j++) {
            float mn = fmaxf(mrow[j], tm[j]);
            fj[j] = __expf(mrow[j] - mn);
            mrow[j] = mn;
        }
        float rs[4] = {0.f, 0.f, 0.f, 0.f};
        #pragma unroll
        for (int mi = 0; mi < 2; mi++)
            #pragma unroll
            for (int ni = 0; ni < 4; ni++) {
                sa[mi][ni][0] = __expf(sa[mi][ni][0] - mrow[mi * 2]);     rs[mi * 2] += sa[mi][ni][0];
                sa[mi][ni][1] = __expf(sa[mi][ni][1] - mrow[mi * 2]);     rs[mi * 2] += sa[mi][ni][1];
                sa[mi][ni][2] = __expf(sa[mi][ni][2] - mrow[mi * 2 + 1]); rs[mi * 2 + 1] += sa[mi][ni][2];
                sa[mi][ni][3] = __expf(sa[mi][ni][3] - mrow[mi * 2 + 1]); rs[mi * 2 + 1] += sa[mi][ni][3];
            }
        #pragma unroll
        for (int j = 0; j < 4; j++) {
            rs[j] += __shfl_xor_sync(0xffffffffu, rs[j], 1);
            rs[j] += __shfl_xor_sync(0xffffffffu, rs[j], 2);
            lrow[j] = lrow[j] * fj[j] + rs[j];
        }
        #pragma unroll
        for (int mi = 0; mi < 2; mi++)
            #pragma unroll
            for (int ni = 0; ni < 16; ni++) {
                o[mi][ni][0] *= fj[mi * 2];     o[mi][ni][1] *= fj[mi * 2];
                o[mi][ni][2] *= fj[mi * 2 + 1]; o[mi][ni][3] *= fj[mi * 2 + 1];
            }
        #pragma unroll
        for (int mi = 0; mi < 2; mi++)
            #pragma unroll
            for (int ni = 0; ni < 4; ni++)
                #pragma unroll
                for (int r = 0; r < 4; r++) sa[mi][ni][r] = f_tf32(sa[mi][ni][r]);

        const int src0 = lr * 4 + (lc >> 1);
        const int src1 = src0 + 2;
        const bool odd = (lc & 1);
        #pragma unroll
        for (int ks = 0; ks < 4; ks++) {
            unsigned a[2][4];
            #pragma unroll
            for (int mi = 0; mi < 2; mi++) {
                float v00 = __shfl_sync(0xffffffffu, sa[mi][ks][0], src0);
                float v01 = __shfl_sync(0xffffffffu, sa[mi][ks][1], src0);
                float v10 = __shfl_sync(0xffffffffu, sa[mi][ks][2], src0);
                float v11 = __shfl_sync(0xffffffffu, sa[mi][ks][3], src0);
                float w00 = __shfl_sync(0xffffffffu, sa[mi][ks][0], src1);
                float w01 = __shfl_sync(0xffffffffu, sa[mi][ks][1], src1);
                float w10 = __shfl_sync(0xffffffffu, sa[mi][ks][2], src1);
                float w11 = __shfl_sync(0xffffffffu, sa[mi][ks][3], src1);
                a[mi][0] = __float_as_uint(odd ? v01 : v00);
                a[mi][1] = __float_as_uint(odd ? v11 : v10);
                a[mi][2] = __float_as_uint(odd ? w01 : w00);
                a[mi][3] = __float_as_uint(odd ? w11 : w10);
            }
            #pragma unroll
            for (int ni = 0; ni < 16; ni++) {
                unsigned bb[2];
                const float* pb = &Vs[(wc * 32 + ks * 8 + lc) * 132 + ni * 8 + lr];
                bb[0] = __float_as_uint(pb[0]);
                bb[1] = __float_as_uint(pb[4 * 132]);
                mma_tf32(o[0][ni], a[0], bb);
                mma_tf32(o[1][ni], a[1], bb);
            }
        }
    }

    __syncthreads();
    if (wc == 1) {
        #pragma unroll
        for (int mi = 0; mi < 2; mi++) {
            int r0 = wr * 32 + mi * 16 + lr;
            #pragma unroll
            for (int ni = 0; ni < 16; ni++) {
                *reinterpret_cast<float2*>(&Qs[r0 * 132 + ni * 8 + 2 * lc]) =
                    make_float2(o[mi][ni][0], o[mi][ni][1]);
                *reinterpret_cast<float2*>(&Qs[(r0 + 8) * 132 + ni * 8 + 2 * lc]) =
                    make_float2(o[mi][ni][2], o[mi][ni][3]);
            }
            if (lc == 0) {
                Qs[r0 * 132 + 128] = mrow[mi * 2];
                Qs[r0 * 132 + 129] = lrow[mi * 2];
                Qs[(r0 + 8) * 132 + 128] = mrow[mi * 2 + 1];
                Qs[(r0 + 8) * 132 + 129] = lrow[mi * 2 + 1];
            }
        }
    }
    __syncthreads();
    if (wc == 0) {
        #pragma unroll
        for (int mi = 0; mi < 2; mi++) {
            #pragma unroll
            for (int half = 0; half < 2; half++) {
                int r0 = wr * 32 + mi * 16 + lr + half * 8;
                int j = mi * 2 + half;
                float m1 = Qs[r0 * 132 + 128];
                float l1 = Qs[r0 * 132 + 129];
                float mm = fmaxf(mrow[j], m1);
                float f0 = __expf(mrow[j] - mm), f1 = __expf(m1 - mm);
                float ll = lrow[j] * f0 + l1 * f1;
                float inv = 1.f / ll;
                int rg = qt * 128 + r0;
                if (rg < N_TOK) {
                    __half* dst = Og + ((size_t)(b * N_TOK + rg)) * C_DIM + h * D_HEAD;
                    #pragma unroll
                    for (int ni = 0; ni < 16; ni++) {
                        float2 o1 = *reinterpret_cast<float2*>(&Qs[r0 * 132 + ni * 8 + 2 * lc]);
                        float v0 = (o[mi][ni][half * 2]     * f0 + o1.x * f1) * inv;
                        float v1 = (o[mi][ni][half * 2 + 1] * f0 + o1.y * f1) * inv;
                        *reinterpret_cast<__half2*>(&dst[ni * 8 + 2 * lc]) =
                            __floats2half2_rn(v0, v1);
                    }
                }
            }
        }
    }
}

// ===================== pre-processing kernels =====================

__global__ void conv_half(const float* __restrict__ in, __half* __restrict__ out, long n4)
{
    long i = (long)blockIdx.x * blockDim.x + threadIdx.x;
    long stride = (long)gridDim.x * blockDim.x;
    for (; i < n4; i += stride) {
        float4 v = reinterpret_cast<const float4*>(in)[i];
        __half2 h0 = __floats2half2_rn(v.x, v.y);
        __half2 h1 = __floats2half2_rn(v.z, v.w);
        reinterpret_cast<__half2*>(out)[i * 2]     = h0;
        reinterpret_cast<__half2*>(out)[i * 2 + 1] = h1;
    }
}

// RMSNorm over full C for q and k segments of one qkv row, in place (tf32-rounded out).
__global__ void rmsnorm_qk(float* __restrict__ qkv,
                           const float* __restrict__ qw, const float* __restrict__ kw)
{
    float* row = qkv + (size_t)blockIdx.x * (3 * C_DIM);
    int tid = threadIdx.x;
    float sq = 0.f, sk = 0.f;
    for (int i = tid * 4; i < C_DIM; i += 256 * 4) {
        float4 q = *reinterpret_cast<const float4*>(row + i);
        float4 k = *reinterpret_cast<const float4*>(row + C_DIM + i);
        sq += q.x * q.x + q.y * q.y + q.z * q.z + q.w * q.w;
        sk += k.x * k.x + k.y * k.y + k.z * k.z + k.w * k.w;
    }
    #pragma unroll
    for (int o = 16; o; o >>= 1) {
        sq += __shfl_xor_sync(0xffffffffu, sq, o);
        sk += __shfl_xor_sync(0xffffffffu, sk, o);
    }
    __shared__ float s1[8], s2[8];
    int lane = tid & 31, warp = tid >> 5;
    if (lane == 0) { s1[warp] = sq; s2[warp] = sk; }
    __syncthreads();
    if (tid == 0) {
        float a = 0.f, b = 0.f;
        #pragma unroll
        for (int w = 0; w < 8; w++) { a += s1[w]; b += s2[w]; }
        s1[0] = rsqrtf(a / C_DIM + 1e-6f);
        s2[0] = rsqrtf(b / C_DIM + 1e-6f);
    }
    __syncthreads();
    float invq = s1[0], invk = s2[0];
    for (int i = tid * 4; i < C_DIM; i += 256 * 4) {
        float4 q = *reinterpret_cast<const float4*>(row + i);
        float4 k = *reinterpret_cast<const float4*>(row + C_DIM + i);
        q.x = f_tf32(q.x * invq * qw[i]);     q.y = f_tf32(q.y * invq * qw[i + 1]);
        q.z = f_tf32(q.z * invq * qw[i + 2]); q.w = f_tf32(q.w * invq * qw[i + 3]);
        k.x = f_tf32(k.x * invk * kw[i]);     k.y = f_tf32(k.y * invk * kw[i + 1]);
        k.z = f_tf32(k.z * invk * kw[i + 2]); k.w = f_tf32(k.w * invk * kw[i + 3]);
        *reinterpret_cast<float4*>(row + i) = q;
        *reinterpret_cast<float4*>(row + C_DIM + i) = k;
    }
}

extern "C" void kernel_launch(void* const* d_in, const int* in_sizes, int n_in,
                              void* d_out, int out_size)
{
    const float* x        = (const float*)d_in[0];
    const float* qkv_w    = (const float*)d_in[1];
    const float* qkv_b    = (const float*)d_in[2];
    const float* q_norm_w = (const float*)d_in[3];
    const float* k_norm_w = (const float*)d_in[4];
    const float* proj_w   = (const float*)d_in[5];
    const float* proj_b   = (const float*)d_in[6];
    float* out = (float*)d_out;

    float *qkvp;
    __half *xh, *wqkvh, *wprojh, *atth;
    cudaGetSymbolAddress((void**)&qkvp,   g_qkv);
    cudaGetSymbolAddress((void**)&xh,     g_xh);
    cudaGetSymbolAddress((void**)&wqkvh,  g_wqkvh);
    cudaGetSymbolAddress((void**)&wprojh, g_wprojh);
    cudaGetSymbolAddress((void**)&atth,   g_atth);

    cudaFuncSetAttribute(hgemm, cudaFuncAttributeMaxDynamicSharedMemorySize, HG_SMEM);
    cudaFuncSetAttribute(flash_attn, cudaFuncAttributeMaxDynamicSharedMemorySize, FA_SMEM);

    dim3 blk(256);

    // 0. Convert operands to fp16 once
    conv_half<<<2048, 256>>>(x, xh, (long)M_ROWS * C_DIM / 4);
    conv_half<<<2048, 256>>>(qkv_w, wqkvh, (long)C_DIM * 3 * C_DIM / 4);
    conv_half<<<2048, 256>>>(proj_w, wprojh, (long)C_DIM * C_DIM / 4);

    // 1. QKV GEMM (fp16 in, f32 out tf32-rounded): [8200,3200] x [3200,9600] + bias
    {
        int TM = (M_ROWS + 127) / 128;          // 65
        int TN = (3 * C_DIM + 255) / 256;       // 38
        hgemm<<<dim3(TM * TN, 1, 1), blk, HG_SMEM>>>(
            xh, wqkvh, qkv_b, qkvp, M_ROWS, 3 * C_DIM, C_DIM,
            C_DIM, 3 * C_DIM, 3 * C_DIM, 1, TM, TN);
    }

    // 2. RMSNorm q,k in place (tf32-rounded out)
    rmsnorm_qk<<<M_ROWS, blk>>>(qkvp, q_norm_w, k_norm_w);

    // 3-5. Fused flash attention -> g_atth (fp16 out)
    flash_attn<<<dim3(9, 200), blk, FA_SMEM>>>(qkvp, atth);

    // 6. Proj GEMM (fp16 in): [8200,3200] x [3200,3200] + bias -> out (f32)
    {
        int TM = (M_ROWS + 127) / 128;          // 65
        int TN = (C_DIM + 255) / 256;           // 13
        hgemm<<<dim3(TM * TN, 1, 1), blk, HG_SMEM>>>(
            atth, wprojh, proj_b, out, M_ROWS, C_DIM, C_DIM,
            C_DIM, C_DIM, C_DIM, 0, TM, TN);
    }
}

// round 11
// speedup vs baseline: 4.6174x; 1.1631x over previous
#include <cuda_runtime.h>
#include <cuda_fp16.h>
#include <math.h>
#include <stdint.h>

// Problem constants
#define H_HEADS 25
#define B_DIM   8
#define N_TOK   1025
#define C_DIM   3200
#define D_HEAD  128
#define M_ROWS  (B_DIM * N_TOK)   // 8200

// Scratch (device globals)
__device__ float  g_qkv[(size_t)M_ROWS * 3 * C_DIM];      // [8200, 9600] f32 (QKV gemm out)
__device__ __half g_qkvh[(size_t)M_ROWS * 3 * C_DIM];     // fp16 qkv (q scaled+normed, k normed, v)
__device__ __half g_xh[(size_t)M_ROWS * C_DIM];           // x in fp16
__device__ __half g_wqkvh[(size_t)C_DIM * 3 * C_DIM];     // qkv_w in fp16
__device__ __half g_wprojh[(size_t)C_DIM * C_DIM];        // proj_w in fp16
__device__ __half g_atth[(size_t)M_ROWS * C_DIM];         // attention out in fp16

__device__ __forceinline__ void cp16(uint32_t dst, const void* src, int bytes) {
    asm volatile("cp.async.cg.shared.global [%0], [%1], 16, %2;\n"
                 :: "r"(dst), "l"(src), "r"(bytes));
}
__device__ __forceinline__ void cp_commit() { asm volatile("cp.async.commit_group;\n" ::); }
template<int NN>
__device__ __forceinline__ void cp_wait() { asm volatile("cp.async.wait_group %0;\n" :: "n"(NN)); }

__device__ __forceinline__ uint32_t smem_u32(const void* p) {
    return (uint32_t)__cvta_generic_to_shared(p);
}

__device__ __forceinline__ void mma_f16(float (&d)[4], const unsigned (&a)[4], const unsigned (&b)[2]) {
    asm volatile(
        "mma.sync.aligned.m16n8k16.row.col.f32.f16.f16.f32 "
        "{%0,%1,%2,%3}, {%4,%5,%6,%7}, {%8,%9}, {%0,%1,%2,%3};"
        : "+f"(d[0]), "+f"(d[1]), "+f"(d[2]), "+f"(d[3])
        : "r"(a[0]), "r"(a[1]), "r"(a[2]), "r"(a[3]), "r"(b[0]), "r"(b[1]));
}

__device__ __forceinline__ unsigned pack_h2(float a, float b) {
    __half2 h = __floats2half2_rn(a, b);
    return *reinterpret_cast<unsigned*>(&h);
}

#define LDSM_X4(r0, r1, r2, r3, addr) \
    asm volatile("ldmatrix.sync.aligned.m8n8.x4.shared.b16 {%0,%1,%2,%3}, [%4];" \
                 : "=r"(r0), "=r"(r1), "=r"(r2), "=r"(r3) : "r"(addr))
#define LDSM_X4_T(r0, r1, r2, r3, addr) \
    asm volatile("ldmatrix.sync.aligned.m8n8.x4.trans.shared.b16 {%0,%1,%2,%3}, [%4];" \
                 : "=r"(r0), "=r"(r1), "=r"(r2), "=r"(r3) : "r"(addr))

// =====================================================================
// FP16 GEMM (validated R9): C[f32] = A[f16 MxK] * B[f16 KxN] + bias
// 128x256x32 tile, 256 thr, warp 64x64, 4-stage cp.async (wait 2).
// =====================================================================
#define HG_ASH  (128 * 40)
#define HG_BSH  (32 * 264)
#define HG_AB   (HG_ASH * 2)         // 10240 bytes
#define HG_STB  ((HG_ASH + HG_BSH) * 2)   // 27136 bytes
#define HG_SMEM (4 * HG_STB)         // 108544 bytes

__global__ void __launch_bounds__(256, 1)
hgemm(const __half* __restrict__ A, const __half* __restrict__ B,
      const float* __restrict__ bias, float* __restrict__ C,
      int M, int N, int K, long lda, long ldb, long ldc, int TM, int TN)
{
    extern __shared__ __half hsm[];

    int tm, tn;
    {
        const int GM = 16;
        int per = GM * TN;
        int g = blockIdx.x / per, r = blockIdx.x - g * per;
        int rows = TM - g * GM; if (rows > GM) rows = GM;
        tm = g * GM + r % rows;
        tn = r / rows;
    }
    const int bm0 = tm * 128;
    const int bn0 = tn * 256;

    const int tid = threadIdx.x;
    const int lane = tid & 31, warp = tid >> 5;
    const int wm = warp & 1, wn = warp >> 1;
    const int lr = lane >> 2, lc = lane & 3;

    const uint32_t smbase = smem_u32(hsm);
    const int j8 = lane >> 3, i8 = lane & 7;
    const uint32_t a_lane = (uint32_t)((wm * 64 + (j8 & 1) * 8 + i8) * 80 + (j8 >> 1) * 16);
    const uint32_t b_lane = (uint32_t)(((j8 & 1) * 8 + i8) * 528 + (wn * 64 + (j8 >> 1) * 8) * 2);

    float acc[4][8][4];
    #pragma unroll
    for (int mi = 0; mi < 4; mi++)
        #pragma unroll
        for (int ni = 0; ni < 8; ni++)
            #pragma unroll
            for (int r = 0; r < 4; r++)
                acc[mi][ni][r] = 0.f;

    const int T = K / 32;

    auto load_tiles = [&](int t, int s) {
        int k0 = t * 32;
        uint32_t ab = smbase + (uint32_t)s * HG_STB;
        uint32_t bb = ab + HG_AB;
        #pragma unroll
        for (int i = 0; i < 2; i++) {
            int f = tid + i * 256;
            int row = f >> 2, c = f & 3;
            int gm = bm0 + row;
            const __half* src = A; int bytes = 0;
            if (gm < M) { src = A + (size_t)gm * lda + k0 + c * 8; bytes = 16; }
            cp16(ab + (uint32_t)(row * 80 + c * 16), src, bytes);
        }
        #pragma unroll
        for (int i = 0; i < 4; i++) {
            int f = tid + i * 256;
            int kr = f >> 5, nc = f & 31;
            int gn = bn0 + nc * 8;
            const __half* src = B; int bytes = 0;
            if (gn < N) { src = B + (size_t)(k0 + kr) * ldb + gn; bytes = 16; }
            cp16(bb + (uint32_t)(kr * 528 + nc * 16), src, bytes);
        }
    };

    load_tiles(0, 0); cp_commit();
    if (T > 1) load_tiles(1, 1);
    cp_commit();
    if (T > 2) load_tiles(2, 2);
    cp_commit();

    for (int t = 0; t < T; t++) {
        if (t + 2 < T) cp_wait<2>(); else if (t + 1 < T) cp_wait<1>(); else cp_wait<0>();
        __syncthreads();
        if (t + 3 < T) { load_tiles(t + 3, (t + 3) & 3); }
        cp_commit();
        uint32_t asb = smbase + (uint32_t)(t & 3) * HG_STB;
        uint32_t bsb = asb + HG_AB;
        #pragma unroll
        for (int ks = 0; ks < 2; ks++) {
            unsigned af[4][4], bf[4][4];
            #pragma unroll
            for (int mi = 0; mi < 4; mi++)
                LDSM_X4(af[mi][0], af[mi][1], af[mi][2], af[mi][3],
                        asb + a_lane + (uint32_t)(mi * 1280 + ks * 32));
            #pragma unroll
            for (int nb = 0; nb < 4; nb++)
                LDSM_X4_T(bf[nb][0], bf[nb][1], bf[nb][2], bf[nb][3],
                          bsb + b_lane + (uint32_t)(nb * 32 + ks * 8448));
            #pragma unroll
            for (int mi = 0; mi < 4; mi++)
                #pragma unroll
                for (int nb = 0; nb < 4; nb++) {
                    unsigned b0[2] = { bf[nb][0], bf[nb][1] };
                    unsigned b1[2] = { bf[nb][2], bf[nb][3] };
                    mma_f16(acc[mi][nb * 2],     af[mi], b0);
                    mma_f16(acc[mi][nb * 2 + 1], af[mi], b1);
                }
        }
    }

    #pragma unroll
    for (int mi = 0; mi < 4; mi++) {
        #pragma unroll
        for (int ni = 0; ni < 8; ni++) {
            int r0 = bm0 + wm * 64 + mi * 16 + lr;
            int c0 = bn0 + wn * 64 + ni * 8 + lc * 2;
            float b0 = 0.f, b1 = 0.f;
            if (bias) {
                if (c0 < N)     b0 = bias[c0];
                if (c0 + 1 < N) b1 = bias[c0 + 1];
            }
            #pragma unroll
            for (int rr = 0; rr < 2; rr++) {
                int rw = r0 + rr * 8;
                if (rw < M) {
                    if (c0 < N)     C[(long)rw * ldc + c0]     = acc[mi][ni][rr * 2]     + b0;
                    if (c0 + 1 < N) C[(long)rw * ldc + c0 + 1] = acc[mi][ni][rr * 2 + 1] + b1;
                }
            }
        }
    }
}

// =====================================================================
// Fused flash attention, full fp16 datapath.
// Warp grid 4 (q-groups of 32) x 2 (kv halves of 32). Q pre-scaled.
// smem: Q[128][136]h + 2 stages of (K[64][136]h, V[64][136]h) + stats.
// Merge buffer (float, stride 132) aliases the KV stage region at the end.
// =====================================================================
#define FAH_QB   (128 * 136 * 2)            // 34816 B
#define FAH_KVB  (64 * 136 * 2)             // 17408 B
#define FAH_SMEM (FAH_QB + 4 * FAH_KVB + 1024)   // 105472 B
#define FA_T     17

__global__ void __launch_bounds__(256, 1)
flash_attn_h(const __half* __restrict__ qkvh, __half* __restrict__ Og)
{
    extern __shared__ char fsm[];
    const uint32_t smb = smem_u32(fsm);
    const int tid = threadIdx.x, w = tid >> 5, lane = tid & 31;
    const int wr = w >> 1, wc = w & 1;
    const int lr = lane >> 2, lc = lane & 3;
    const int j8 = lane >> 3, i8 = lane & 7;
    const int qt = blockIdx.x, bh = blockIdx.y;
    const int b = bh / H_HEADS, h = bh - b * H_HEADS;

    const __half* qbase = qkvh + (size_t)b * N_TOK * (3 * C_DIM) + h * D_HEAD;

    // ldmatrix lane address components (byte offsets within region)
    const uint32_t qa_lane = (uint32_t)((wr * 32 + (j8 & 1) * 8 + i8) * 272 + (j8 >> 1) * 16);
    const uint32_t kb_lane = (uint32_t)((wc * 32 + (j8 & 1) * 8 + i8) * 272 + (j8 >> 1) * 16);
    const uint32_t vb_lane = (uint32_t)(((wc * 32 + (j8 & 1) * 8 + i8) * 272) + ((j8 >> 1) * 8) * 2);

    // ---- load Q tile (128 rows x 128 halfs) ----
    #pragma unroll
    for (int i = 0; i < 8; i++) {
        int id = tid + i * 256;
        int r = id >> 4, c = id & 15;
        int q = qt * 128 + r;
        const __half* src = qbase; int bytes = 0;
        if (q < N_TOK) { src = qbase + (size_t)q * (3 * C_DIM) + c * 8; bytes = 16; }
        cp16(smb + (uint32_t)(r * 272 + c * 16), src, bytes);
    }
    auto load_kv = [&](int t, int s) {
        uint32_t kb = smb + FAH_QB + (uint32_t)s * 2 * FAH_KVB;
        uint32_t vb = kb + FAH_KVB;
        #pragma unroll
        for (int i = 0; i < 4; i++) {
            int id = tid + i * 256;
            int r = id >> 4, c = id & 15;
            int kv = t * 64 + r;
            const __half* srck = qbase; const __half* srcv = qbase; int bytes = 0;
            if (kv < N_TOK) {
                srck = qbase + (size_t)kv * (3 * C_DIM) + C_DIM + c * 8;
                srcv = qbase + (size_t)kv * (3 * C_DIM) + 2 * C_DIM + c * 8;
                bytes = 16;
            }
            cp16(kb + (uint32_t)(r * 272 + c * 16), srck, bytes);
            cp16(vb + (uint32_t)(r * 272 + c * 16), srcv, bytes);
        }
    };
    load_kv(0, 0);
    cp_commit();

    float o[2][16][4];
    #pragma unroll
    for (int mi = 0; mi < 2; mi++)
        #pragma unroll
        for (int ni = 0; ni < 16; ni++)
            #pragma unroll
            for (int r = 0; r < 4; r++) o[mi][ni][r] = 0.f;
    float mrow[4] = {-1e30f, -1e30f, -1e30f, -1e30f};
    float lrow[4] = {0.f, 0.f, 0.f, 0.f};

    for (int t = 0; t < FA_T; t++) {
        int s = t & 1;
        cp_wait<0>();
        __syncthreads();
        if (t + 1 < FA_T) load_kv(t + 1, s ^ 1);
        cp_commit();

        uint32_t kb = smb + FAH_QB + (uint32_t)s * 2 * FAH_KVB;
        uint32_t vb = kb + FAH_KVB;

        // ---- S = Q K^T (warp: 32 q x 32 kv, k=128 -> 8 k16 steps) ----
        float sa[2][4][4];
        #pragma unroll
        for (int mi = 0; mi < 2; mi++)
            #pragma unroll
            for (int ni = 0; ni < 4; ni++)
                #pragma unroll
                for (int r = 0; r < 4; r++) sa[mi][ni][r] = 0.f;

        #pragma unroll
        for (int ks = 0; ks < 8; ks++) {
            unsigned af[2][4], kf[2][4];
            #pragma unroll
            for (int mi = 0; mi < 2; mi++)
                LDSM_X4(af[mi][0], af[mi][1], af[mi][2], af[mi][3],
                        smb + qa_lane + (uint32_t)(mi * 16 * 272 + ks * 32));
            #pragma unroll
            for (int g = 0; g < 2; g++)
                LDSM_X4(kf[g][0], kf[g][1], kf[g][2], kf[g][3],
                        kb + kb_lane + (uint32_t)(g * 16 * 272 + ks * 32));
            #pragma unroll
            for (int mi = 0; mi < 2; mi++)
                #pragma unroll
                for (int g = 0; g < 2; g++) {
                    unsigned b0[2] = { kf[g][0], kf[g][2] };   // n-block g*2
                    unsigned b1[2] = { kf[g][1], kf[g][3] };   // n-block g*2+1
                    mma_f16(sa[mi][g * 2],     af[mi], b0);
                    mma_f16(sa[mi][g * 2 + 1], af[mi], b1);
                }
        }

        // ---- mask (Q pre-scaled; no scale here) ----
        if (t == FA_T - 1) {
            #pragma unroll
            for (int ni = 0; ni < 4; ni++) {
                int col = t * 64 + wc * 32 + ni * 8 + 2 * lc;
                if (col >= N_TOK) {
                    #pragma unroll
                    for (int mi = 0; mi < 2; mi++) { sa[mi][ni][0] = -1e30f; sa[mi][ni][2] = -1e30f; }
                }
                if (col + 1 >= N_TOK) {
                    #pragma unroll
                    for (int mi = 0; mi < 2; mi++) { sa[mi][ni][1] = -1e30f; sa[mi][ni][3] = -1e30f; }
                }
            }
        }

        // ---- online softmax (warp-local, 4 row-stats per lane) ----
        float tm[4] = {-1e30f, -1e30f, -1e30f, -1e30f};
        #pragma unroll
        for (int mi = 0; mi < 2; mi++)
            #pragma unroll
            for (int ni = 0; ni < 4; ni++) {
                tm[mi * 2 + 0] = fmaxf(tm[mi * 2 + 0], fmaxf(sa[mi][ni][0], sa[mi][ni][1]));
                tm[mi * 2 + 1] = fmaxf(tm[mi * 2 + 1], fmaxf(sa[mi][ni][2], sa[mi][ni][3]));
            }
        #pragma unroll
        for (int j = 0; j < 4; j++) {
            tm[j] = fmaxf(tm[j], __shfl_xor_sync(0xffffffffu, tm[j], 1));
            tm[j] = fmaxf(tm[j], __shfl_xor_sync(0xffffffffu, tm[j], 2));
        }
        float fj[4];
        #pragma unroll
        for (int j = 0; j < 4; j++) {
            float mn = fmaxf(mrow[j], tm[j]);
            fj[j] = __expf(mrow[j] - mn);
            mrow[j] = mn;
        }
        float rs[4] = {0.f, 0.f, 0.f, 0.f};
        #pragma unroll
        for (int mi = 0; mi < 2; mi++)
            #pragma unroll
            for (int ni = 0; ni < 4; ni++) {
                sa[mi][ni][0] = __expf(sa[mi][ni][0] - mrow[mi * 2]);     rs[mi * 2] += sa[mi][ni][0];
                sa[mi][ni][1] = __expf(sa[mi][ni][1] - mrow[mi * 2]);     rs[mi * 2] += sa[mi][ni][1];
                sa[mi][ni][2] = __expf(sa[mi][ni][2] - mrow[mi * 2 + 1]); rs[mi * 2 + 1] += sa[mi][ni][2];
                sa[mi][ni][3] = __expf(sa[mi][ni][3] - mrow[mi * 2 + 1]); rs[mi * 2 + 1] += sa[mi][ni][3];
            }
        #pragma unroll
        for (int j = 0; j < 4; j++) {
            rs[j] += __shfl_xor_sync(0xffffffffu, rs[j], 1);
            rs[j] += __shfl_xor_sync(0xffffffffu, rs[j], 2);
            lrow[j] = lrow[j] * fj[j] + rs[j];
        }
        #pragma unroll
        for (int mi = 0; mi < 2; mi++)
            #pragma unroll
            for (int ni = 0; ni < 16; ni++) {
                o[mi][ni][0] *= fj[mi * 2];     o[mi][ni][1] *= fj[mi * 2];
                o[mi][ni][2] *= fj[mi * 2 + 1]; o[mi][ni][3] *= fj[mi * 2 + 1];
            }

        // ---- O += P V  (k=32 -> 2 k16 steps; P c-frag -> a-frag, no shfl) ----
        #pragma unroll
        for (int ks2 = 0; ks2 < 2; ks2++) {
            unsigned a[2][4];
            #pragma unroll
            for (int mi = 0; mi < 2; mi++) {
                a[mi][0] = pack_h2(sa[mi][2 * ks2][0],     sa[mi][2 * ks2][1]);
                a[mi][1] = pack_h2(sa[mi][2 * ks2][2],     sa[mi][2 * ks2][3]);
                a[mi][2] = pack_h2(sa[mi][2 * ks2 + 1][0], sa[mi][2 * ks2 + 1][1]);
                a[mi][3] = pack_h2(sa[mi][2 * ks2 + 1][2], sa[mi][2 * ks2 + 1][3]);
            }
            #pragma unroll
            for (int nb = 0; nb < 8; nb++) {
                unsigned vf[4];
                LDSM_X4_T(vf[0], vf[1], vf[2], vf[3],
                          vb + vb_lane + (uint32_t)(ks2 * 16 * 272 + nb * 32));
                unsigned b0[2] = { vf[0], vf[1] };
                unsigned b1[2] = { vf[2], vf[3] };
                #pragma unroll
                for (int mi = 0; mi < 2; mi++) {
                    mma_f16(o[mi][nb * 2],     a[mi], b0);
                    mma_f16(o[mi][nb * 2 + 1], a[mi], b1);
                }
            }
        }
    }

    // ---- split-KV merge via float buffer aliasing KV region ----
    float* Ms = reinterpret_cast<float*>(fsm + FAH_QB);            // [128][132] floats
    float* stats = reinterpret_cast<float*>(fsm + FAH_QB + 128 * 132 * 4);  // [128][2]
    __syncthreads();
    if (wc == 1) {
        #pragma unroll
        for (int mi = 0; mi < 2; mi++) {
            int r0 = wr * 32 + mi * 16 + lr;
            #pragma unroll
            for (int ni = 0; ni < 16; ni++) {
                *reinterpret_cast<float2*>(&Ms[r0 * 132 + ni * 8 + 2 * lc]) =
                    make_float2(o[mi][ni][0], o[mi][ni][1]);
                *reinterpret_cast<float2*>(&Ms[(r0 + 8) * 132 + ni * 8 + 2 * lc]) =
                    make_float2(o[mi][ni][2], o[mi][ni][3]);
            }
            if (lc == 0) {
                stats[r0 * 2]           = mrow[mi * 2];
                stats[r0 * 2 + 1]       = lrow[mi * 2];
                stats[(r0 + 8) * 2]     = mrow[mi * 2 + 1];
                stats[(r0 + 8) * 2 + 1] = lrow[mi * 2 + 1];
            }
        }
    }
    __syncthreads();
    if (wc == 0) {
        #pragma unroll
        for (int mi = 0; mi < 2; mi++) {
            #pragma unroll
            for (int half = 0; half < 2; half++) {
                int r0 = wr * 32 + mi * 16 + lr + half * 8;
                int j = mi * 2 + half;
                float m1 = stats[r0 * 2];
                float l1 = stats[r0 * 2 + 1];
                float mm = fmaxf(mrow[j], m1);
                float f0 = __expf(mrow[j] - mm), f1 = __expf(m1 - mm);
                float ll = lrow[j] * f0 + l1 * f1;
                float inv = 1.f / ll;
                int rg = qt * 128 + r0;
                if (rg < N_TOK) {
                    __half* dst = Og + ((size_t)(b * N_TOK + rg)) * C_DIM + h * D_HEAD;
                    #pragma unroll
                    for (int ni = 0; ni < 16; ni++) {
                        float2 o1 = *reinterpret_cast<float2*>(&Ms[r0 * 132 + ni * 8 + 2 * lc]);
                        float v0 = (o[mi][ni][half * 2]     * f0 + o1.x * f1) * inv;
                        float v1 = (o[mi][ni][half * 2 + 1] * f0 + o1.y * f1) * inv;
                        *reinterpret_cast<__half2*>(&dst[ni * 8 + 2 * lc]) =
                            __floats2half2_rn(v0, v1);
                    }
                }
            }
        }
    }
}

// ===================== pre-processing kernels =====================

__global__ void conv_half(const float* __restrict__ in, __half* __restrict__ out, long n4)
{
    long i = (long)blockIdx.x * blockDim.x + threadIdx.x;
    long stride = (long)gridDim.x * blockDim.x;
    for (; i < n4; i += stride) {
        float4 v = reinterpret_cast<const float4*>(in)[i];
        reinterpret_cast<__half2*>(out)[i * 2]     = __floats2half2_rn(v.x, v.y);
        reinterpret_cast<__half2*>(out)[i * 2 + 1] = __floats2half2_rn(v.z, v.w);
    }
}

// RMSNorm q,k over full C; emits fp16 qkv row (q scaled by 1/sqrt(D), v converted).
__global__ void rmsnorm_qk_h(const float* __restrict__ qkv, __half* __restrict__ qkvh,
                             const float* __restrict__ qw, const float* __restrict__ kw)
{
    const float* row = qkv + (size_t)blockIdx.x * (3 * C_DIM);
    __half* orow = qkvh + (size_t)blockIdx.x * (3 * C_DIM);
    int tid = threadIdx.x;
    const float scale = 0.088388347648318447f;   // 1/sqrt(128)
    float sq = 0.f, sk = 0.f;
    for (int i = tid * 4; i < C_DIM; i += 256 * 4) {
        float4 q = *reinterpret_cast<const float4*>(row + i);
        float4 k = *reinterpret_cast<const float4*>(row + C_DIM + i);
        sq += q.x * q.x + q.y * q.y + q.z * q.z + q.w * q.w;
        sk += k.x * k.x + k.y * k.y + k.z * k.z + k.w * k.w;
    }
    #pragma unroll
    for (int o = 16; o; o >>= 1) {
        sq += __shfl_xor_sync(0xffffffffu, sq, o);
        sk += __shfl_xor_sync(0xffffffffu, sk, o);
    }
    __shared__ float s1[8], s2[8];
    int lane = tid & 31, warp = tid >> 5;
    if (lane == 0) { s1[warp] = sq; s2[warp] = sk; }
    __syncthreads();
    if (tid == 0) {
        float a = 0.f, b = 0.f;
        #pragma unroll
        for (int w = 0; w < 8; w++) { a += s1[w]; b += s2[w]; }
        s1[0] = rsqrtf(a / C_DIM + 1e-6f);
        s2[0] = rsqrtf(b / C_DIM + 1e-6f);
    }
    __syncthreads();
    float invq = s1[0] * scale, invk = s2[0];
    for (int i = tid * 4; i < C_DIM; i += 256 * 4) {
        float4 q = *reinterpret_cast<const float4*>(row + i);
        float4 k = *reinterpret_cast<const float4*>(row + C_DIM + i);
        float4 v = *reinterpret_cast<const float4*>(row + 2 * C_DIM + i);
        __half2 q0 = __floats2half2_rn(q.x * invq * qw[i],     q.y * invq * qw[i + 1]);
        __half2 q1 = __floats2half2_rn(q.z * invq * qw[i + 2], q.w * invq * qw[i + 3]);
        __half2 k0 = __floats2half2_rn(k.x * invk * kw[i],     k.y * invk * kw[i + 1]);
        __half2 k1 = __floats2half2_rn(k.z * invk * kw[i + 2], k.w * invk * kw[i + 3]);
        *reinterpret_cast<__half2*>(orow + i)     = q0;
        *reinterpret_cast<__half2*>(orow + i + 2) = q1;
        *reinterpret_cast<__half2*>(orow + C_DIM + i)     = k0;
        *reinterpret_cast<__half2*>(orow + C_DIM + i + 2) = k1;
        *reinterpret_cast<__half2*>(orow + 2 * C_DIM + i)     = __floats2half2_rn(v.x, v.y);
        *reinterpret_cast<__half2*>(orow + 2 * C_DIM + i + 2) = __floats2half2_rn(v.z, v.w);
    }
}

extern "C" void kernel_launch(void* const* d_in, const int* in_sizes, int n_in,
                              void* d_out, int out_size)
{
    const float* x        = (const float*)d_in[0];
    const float* qkv_w    = (const float*)d_in[1];
    const float* qkv_b    = (const float*)d_in[2];
    const float* q_norm_w = (const float*)d_in[3];
    const float* k_norm_w = (const float*)d_in[4];
    const float* proj_w   = (const float*)d_in[5];
    const float* proj_b   = (const float*)d_in[6];
    float* out = (float*)d_out;

    float *qkvp;
    __half *qkvh, *xh, *wqkvh, *wprojh, *atth;
    cudaGetSymbolAddress((void**)&qkvp,   g_qkv);
    cudaGetSymbolAddress((void**)&qkvh,   g_qkvh);
    cudaGetSymbolAddress((void**)&xh,     g_xh);
    cudaGetSymbolAddress((void**)&wqkvh,  g_wqkvh);
    cudaGetSymbolAddress((void**)&wprojh, g_wprojh);
    cudaGetSymbolAddress((void**)&atth,   g_atth);

    cudaFuncSetAttribute(hgemm, cudaFuncAttributeMaxDynamicSharedMemorySize, HG_SMEM);
    cudaFuncSetAttribute(flash_attn_h, cudaFuncAttributeMaxDynamicSharedMemorySize, FAH_SMEM);

    dim3 blk(256);

    // 0. Convert GEMM operands to fp16
    conv_half<<<2048, 256>>>(x, xh, (long)M_ROWS * C_DIM / 4);
    conv_half<<<2048, 256>>>(qkv_w, wqkvh, (long)C_DIM * 3 * C_DIM / 4);
    conv_half<<<2048, 256>>>(proj_w, wprojh, (long)C_DIM * C_DIM / 4);

    // 1. QKV GEMM (fp16 in, f32 out): [8200,3200] x [3200,9600] + bias
    {
        int TM = (M_ROWS + 127) / 128;          // 65
        int TN = (3 * C_DIM + 255) / 256;       // 38
        hgemm<<<dim3(TM * TN, 1, 1), blk, HG_SMEM>>>(
            xh, wqkvh, qkv_b, qkvp, M_ROWS, 3 * C_DIM, C_DIM,
            C_DIM, 3 * C_DIM, 3 * C_DIM, TM, TN);
    }

    // 2. RMSNorm q,k -> fp16 qkv (q pre-scaled)
    rmsnorm_qk_h<<<M_ROWS, blk>>>(qkvp, qkvh, q_norm_w, k_norm_w);

    // 3-5. Fused flash attention (fp16) -> g_atth
    flash_attn_h<<<dim3(9, 200), blk, FAH_SMEM>>>(qkvh, atth);

    // 6. Proj GEMM (fp16 in): [8200,3200] x [3200,3200] + bias -> out (f32)
    {
        int TM = (M_ROWS + 127) / 128;          // 65
        int TN = (C_DIM + 255) / 256;           // 13
        hgemm<<<dim3(TM * TN, 1, 1), blk, HG_SMEM>>>(
            atth, wprojh, proj_b, out, M_ROWS, C_DIM, C_DIM,
            C_DIM, C_DIM, C_DIM, TM, TN);
    }
}

// round 12
// speedup vs baseline: 5.3632x; 1.1615x over previous
#include <cuda_runtime.h>
#include <cuda_fp16.h>
#include <math.h>
#include <stdint.h>

// Problem constants
#define H_HEADS 25
#define B_DIM   8
#define N_TOK   1025
#define C_DIM   3200
#define D_HEAD  128
#define M_ROWS  (B_DIM * N_TOK)   // 8200

// Scratch (device globals)
__device__ __half g_qkvh[(size_t)M_ROWS * 3 * C_DIM];     // fp16 qkv (normed in place)
__device__ __half g_xh[(size_t)M_ROWS * C_DIM];           // x in fp16
__device__ __half g_wqkvh[(size_t)C_DIM * 3 * C_DIM];     // qkv_w in fp16
__device__ __half g_wprojh[(size_t)C_DIM * C_DIM];        // proj_w in fp16
__device__ __half g_atth[(size_t)M_ROWS * C_DIM];         // attention out in fp16

__device__ __forceinline__ void cp16(uint32_t dst, const void* src, int bytes) {
    asm volatile("cp.async.cg.shared.global [%0], [%1], 16, %2;\n"
                 :: "r"(dst), "l"(src), "r"(bytes));
}
__device__ __forceinline__ void cp_commit() { asm volatile("cp.async.commit_group;\n" ::); }
template<int NN>
__device__ __forceinline__ void cp_wait() { asm volatile("cp.async.wait_group %0;\n" :: "n"(NN)); }

__device__ __forceinline__ uint32_t smem_u32(const void* p) {
    return (uint32_t)__cvta_generic_to_shared(p);
}

__device__ __forceinline__ void mma_f16(float (&d)[4], const unsigned (&a)[4], const unsigned (&b)[2]) {
    asm volatile(
        "mma.sync.aligned.m16n8k16.row.col.f32.f16.f16.f32 "
        "{%0,%1,%2,%3}, {%4,%5,%6,%7}, {%8,%9}, {%0,%1,%2,%3};"
        : "+f"(d[0]), "+f"(d[1]), "+f"(d[2]), "+f"(d[3])
        : "r"(a[0]), "r"(a[1]), "r"(a[2]), "r"(a[3]), "r"(b[0]), "r"(b[1]));
}

__device__ __forceinline__ unsigned pack_h2(float a, float b) {
    __half2 h = __floats2half2_rn(a, b);
    return *reinterpret_cast<unsigned*>(&h);
}

#define LDSM_X4(r0, r1, r2, r3, addr) \
    asm volatile("ldmatrix.sync.aligned.m8n8.x4.shared.b16 {%0,%1,%2,%3}, [%4];" \
                 : "=r"(r0), "=r"(r1), "=r"(r2), "=r"(r3) : "r"(addr))
#define LDSM_X4_T(r0, r1, r2, r3, addr) \
    asm volatile("ldmatrix.sync.aligned.m8n8.x4.trans.shared.b16 {%0,%1,%2,%3}, [%4];" \
                 : "=r"(r0), "=r"(r1), "=r"(r2), "=r"(r3) : "r"(addr))

// =====================================================================
// FP16 GEMM, 128x128x32 CTA tile, 2 CTAs/SM, warp tile 64x32 (2x4 grid).
// 4-stage cp.async pipeline (wait 2). Output f32 or fp16 (OutT).
// A smem: [128][40]h (80B rows); B smem: [32][136]h (272B rows).
// =====================================================================
#define HG_AB   (128 * 40 * 2)               // 10240 B
#define HG_BB   (32 * 136 * 2)               // 8704 B
#define HG_STB  (HG_AB + HG_BB)              // 18944 B
#define HG_SMEM (4 * HG_STB)                 // 75776 B

template<typename OutT>
__global__ void __launch_bounds__(256, 2)
hgemm(const __half* __restrict__ A, const __half* __restrict__ B,
      const float* __restrict__ bias, OutT* __restrict__ C,
      int M, int N, int K, long lda, long ldb, long ldc, int TM, int TN)
{
    extern __shared__ __half hsm[];

    int tm, tn;
    {
        const int GM = 16;
        int per = GM * TN;
        int g = blockIdx.x / per, r = blockIdx.x - g * per;
        int rows = TM - g * GM; if (rows > GM) rows = GM;
        tm = g * GM + r % rows;
        tn = r / rows;
    }
    const int bm0 = tm * 128;
    const int bn0 = tn * 128;

    const int tid = threadIdx.x;
    const int lane = tid & 31, warp = tid >> 5;
    const int wm = warp & 1, wn = warp >> 1;      // 2 x 4 warp grid
    const int lr = lane >> 2, lc = lane & 3;

    const uint32_t smbase = smem_u32(hsm);
    const int j8 = lane >> 3, i8 = lane & 7;
    const uint32_t a_lane = (uint32_t)((wm * 64 + (j8 & 1) * 8 + i8) * 80 + (j8 >> 1) * 16);
    const uint32_t b_lane = (uint32_t)(((j8 & 1) * 8 + i8) * 272 + (wn * 32 + (j8 >> 1) * 8) * 2);

    float acc[4][4][4];
    #pragma unroll
    for (int mi = 0; mi < 4; mi++)
        #pragma unroll
        for (int ni = 0; ni < 4; ni++)
            #pragma unroll
            for (int r = 0; r < 4; r++)
                acc[mi][ni][r] = 0.f;

    const int T = K / 32;

    auto load_tiles = [&](int t, int s) {
        int k0 = t * 32;
        uint32_t ab = smbase + (uint32_t)s * HG_STB;
        uint32_t bb = ab + HG_AB;
        // A tile: 128 rows x 4 chunks -> 2 iters
        #pragma unroll
        for (int i = 0; i < 2; i++) {
            int f = tid + i * 256;
            int row = f >> 2, c = f & 3;
            int gm = bm0 + row;
            const __half* src = A; int bytes = 0;
            if (gm < M) { src = A + (size_t)gm * lda + k0 + c * 8; bytes = 16; }
            cp16(ab + (uint32_t)(row * 80 + c * 16), src, bytes);
        }
        // B tile: 32 rows(k) x 16 chunks -> 2 iters
        #pragma unroll
        for (int i = 0; i < 2; i++) {
            int f = tid + i * 256;
            int kr = f >> 4, nc = f & 15;
            int gn = bn0 + nc * 8;
            const __half* src = B; int bytes = 0;
            if (gn < N) { src = B + (size_t)(k0 + kr) * ldb + gn; bytes = 16; }
            cp16(bb + (uint32_t)(kr * 272 + nc * 16), src, bytes);
        }
    };

    load_tiles(0, 0); cp_commit();
    if (T > 1) load_tiles(1, 1);
    cp_commit();
    if (T > 2) load_tiles(2, 2);
    cp_commit();

    for (int t = 0; t < T; t++) {
        if (t + 2 < T) cp_wait<2>(); else if (t + 1 < T) cp_wait<1>(); else cp_wait<0>();
        __syncthreads();
        if (t + 3 < T) { load_tiles(t + 3, (t + 3) & 3); }
        cp_commit();
        uint32_t asb = smbase + (uint32_t)(t & 3) * HG_STB;
        uint32_t bsb = asb + HG_AB;
        #pragma unroll
        for (int ks = 0; ks < 2; ks++) {
            unsigned af[4][4], bf[2][4];
            #pragma unroll
            for (int mi = 0; mi < 4; mi++)
                LDSM_X4(af[mi][0], af[mi][1], af[mi][2], af[mi][3],
                        asb + a_lane + (uint32_t)(mi * 1280 + ks * 32));
            #pragma unroll
            for (int nb = 0; nb < 2; nb++)
                LDSM_X4_T(bf[nb][0], bf[nb][1], bf[nb][2], bf[nb][3],
                          bsb + b_lane + (uint32_t)(nb * 32 + ks * 4352));
            #pragma unroll
            for (int mi = 0; mi < 4; mi++)
                #pragma unroll
                for (int nb = 0; nb < 2; nb++) {
                    unsigned b0[2] = { bf[nb][0], bf[nb][1] };
                    unsigned b1[2] = { bf[nb][2], bf[nb][3] };
                    mma_f16(acc[mi][nb * 2],     af[mi], b0);
                    mma_f16(acc[mi][nb * 2 + 1], af[mi], b1);
                }
        }
    }

    #pragma unroll
    for (int mi = 0; mi < 4; mi++) {
        #pragma unroll
        for (int ni = 0; ni < 4; ni++) {
            int r0 = bm0 + wm * 64 + mi * 16 + lr;
            int c0 = bn0 + wn * 32 + ni * 8 + lc * 2;
            float b0 = 0.f, b1 = 0.f;
            if (bias && c0 < N) { b0 = bias[c0]; b1 = bias[c0 + 1]; }
            #pragma unroll
            for (int rr = 0; rr < 2; rr++) {
                int rw = r0 + rr * 8;
                if (rw < M && c0 < N) {
                    float v0 = acc[mi][ni][rr * 2]     + b0;
                    float v1 = acc[mi][ni][rr * 2 + 1] + b1;
                    if constexpr (sizeof(OutT) == 2) {
                        *reinterpret_cast<__half2*>(
                            reinterpret_cast<__half*>(C) + (size_t)rw * ldc + c0) =
                            __floats2half2_rn(v0, v1);
                    } else {
                        reinterpret_cast<float*>(C)[(size_t)rw * ldc + c0]     = v0;
                        reinterpret_cast<float*>(C)[(size_t)rw * ldc + c0 + 1] = v1;
                    }
                }
            }
        }
    }
}

// =====================================================================
// Fused flash attention, full fp16 datapath (validated R11).
// =====================================================================
#define FAH_QB   (128 * 136 * 2)
#define FAH_KVB  (64 * 136 * 2)
#define FAH_SMEM (FAH_QB + 4 * FAH_KVB + 1024)
#define FA_T     17

__global__ void __launch_bounds__(256, 1)
flash_attn_h(const __half* __restrict__ qkvh, __half* __restrict__ Og)
{
    extern __shared__ char fsm[];
    const uint32_t smb = smem_u32(fsm);
    const int tid = threadIdx.x, w = tid >> 5, lane = tid & 31;
    const int wr = w >> 1, wc = w & 1;
    const int lr = lane >> 2, lc = lane & 3;
    const int j8 = lane >> 3, i8 = lane & 7;
    const int qt = blockIdx.x, bh = blockIdx.y;
    const int b = bh / H_HEADS, h = bh - b * H_HEADS;

    const __half* qbase = qkvh + (size_t)b * N_TOK * (3 * C_DIM) + h * D_HEAD;

    const uint32_t qa_lane = (uint32_t)((wr * 32 + (j8 & 1) * 8 + i8) * 272 + (j8 >> 1) * 16);
    const uint32_t kb_lane = (uint32_t)((wc * 32 + (j8 & 1) * 8 + i8) * 272 + (j8 >> 1) * 16);
    const uint32_t vb_lane = (uint32_t)(((wc * 32 + (j8 & 1) * 8 + i8) * 272) + ((j8 >> 1) * 8) * 2);

    #pragma unroll
    for (int i = 0; i < 8; i++) {
        int id = tid + i * 256;
        int r = id >> 4, c = id & 15;
        int q = qt * 128 + r;
        const __half* src = qbase; int bytes = 0;
        if (q < N_TOK) { src = qbase + (size_t)q * (3 * C_DIM) + c * 8; bytes = 16; }
        cp16(smb + (uint32_t)(r * 272 + c * 16), src, bytes);
    }
    auto load_kv = [&](int t, int s) {
        uint32_t kb = smb + FAH_QB + (uint32_t)s * 2 * FAH_KVB;
        uint32_t vb = kb + FAH_KVB;
        #pragma unroll
        for (int i = 0; i < 4; i++) {
            int id = tid + i * 256;
            int r = id >> 4, c = id & 15;
            int kv = t * 64 + r;
            const __half* srck = qbase; const __half* srcv = qbase; int bytes = 0;
            if (kv < N_TOK) {
                srck = qbase + (size_t)kv * (3 * C_DIM) + C_DIM + c * 8;
                srcv = qbase + (size_t)kv * (3 * C_DIM) + 2 * C_DIM + c * 8;
                bytes = 16;
            }
            cp16(kb + (uint32_t)(r * 272 + c * 16), srck, bytes);
            cp16(vb + (uint32_t)(r * 272 + c * 16), srcv, bytes);
        }
    };
    load_kv(0, 0);
    cp_commit();

    float o[2][16][4];
    #pragma unroll
    for (int mi = 0; mi < 2; mi++)
        #pragma unroll
        for (int ni = 0; ni < 16; ni++)
            #pragma unroll
            for (int r = 0; r < 4; r++) o[mi][ni][r] = 0.f;
    float mrow[4] = {-1e30f, -1e30f, -1e30f, -1e30f};
    float lrow[4] = {0.f, 0.f, 0.f, 0.f};

    for (int t = 0; t < FA_T; t++) {
        int s = t & 1;
        cp_wait<0>();
        __syncthreads();
        if (t + 1 < FA_T) load_kv(t + 1, s ^ 1);
        cp_commit();

        uint32_t kb = smb + FAH_QB + (uint32_t)s * 2 * FAH_KVB;
        uint32_t vb = kb + FAH_KVB;

        float sa[2][4][4];
        #pragma unroll
        for (int mi = 0; mi < 2; mi++)
            #pragma unroll
            for (int ni = 0; ni < 4; ni++)
                #pragma unroll
                for (int r = 0; r < 4; r++) sa[mi][ni][r] = 0.f;

        #pragma unroll
        for (int ks = 0; ks < 8; ks++) {
            unsigned af[2][4], kf[2][4];
            #pragma unroll
            for (int mi = 0; mi < 2; mi++)
                LDSM_X4(af[mi][0], af[mi][1], af[mi][2], af[mi][3],
                        smb + qa_lane + (uint32_t)(mi * 16 * 272 + ks * 32));
            #pragma unroll
            for (int g = 0; g < 2; g++)
                LDSM_X4(kf[g][0], kf[g][1], kf[g][2], kf[g][3],
                        kb + kb_lane + (uint32_t)(g * 16 * 272 + ks * 32));
            #pragma unroll
            for (int mi = 0; mi < 2; mi++)
                #pragma unroll
                for (int g = 0; g < 2; g++) {
                    unsigned b0[2] = { kf[g][0], kf[g][2] };
                    unsigned b1[2] = { kf[g][1], kf[g][3] };
                    mma_f16(sa[mi][g * 2],     af[mi], b0);
                    mma_f16(sa[mi][g * 2 + 1], af[mi], b1);
                }
        }

        if (t == FA_T - 1) {
            #pragma unroll
            for (int ni = 0; ni < 4; ni++) {
                int col = t * 64 + wc * 32 + ni * 8 + 2 * lc;
                if (col >= N_TOK) {
                    #pragma unroll
                    for (int mi = 0; mi < 2; mi++) { sa[mi][ni][0] = -1e30f; sa[mi][ni][2] = -1e30f; }
                }
                if (col + 1 >= N_TOK) {
                    #pragma unroll
                    for (int mi = 0; mi < 2; mi++) { sa[mi][ni][1] = -1e30f; sa[mi][ni][3] = -1e30f; }
                }
            }
        }

        float tm[4] = {-1e30f, -1e30f, -1e30f, -1e30f};
        #pragma unroll
        for (int mi = 0; mi < 2; mi++)
            #pragma unroll
            for (int ni = 0; ni < 4; ni++) {
                tm[mi * 2 + 0] = fmaxf(tm[mi * 2 + 0], fmaxf(sa[mi][ni][0], sa[mi][ni][1]));
                tm[mi * 2 + 1] = fmaxf(tm[mi * 2 + 1], fmaxf(sa[mi][ni][2], sa[mi][ni][3]));
            }
        #pragma unroll
        for (int j = 0; j < 4; j++) {
            tm[j] = fmaxf(tm[j], __shfl_xor_sync(0xffffffffu, tm[j], 1));
            tm[j] = fmaxf(tm[j], __shfl_xor_sync(0xffffffffu, tm[j], 2));
        }
        float fj[4];
        #pragma unroll
        for (int j = 0; j < 4; j++) {
            float mn = fmaxf(mrow[j], tm[j]);
            fj[j] = __expf(mrow[j] - mn);
            mrow[j] = mn;
        }
        float rs[4] = {0.f, 0.f, 0.f, 0.f};
        #pragma unroll
        for (int mi = 0; mi < 2; mi++)
            #pragma unroll
            for (int ni = 0; ni < 4; ni++) {
                sa[mi][ni][0] = __expf(sa[mi][ni][0] - mrow[mi * 2]);     rs[mi * 2] += sa[mi][ni][0];
                sa[mi][ni][1] = __expf(sa[mi][ni][1] - mrow[mi * 2]);     rs[mi * 2] += sa[mi][ni][1];
                sa[mi][ni][2] = __expf(sa[mi][ni][2] - mrow[mi * 2 + 1]); rs[mi * 2 + 1] += sa[mi][ni][2];
                sa[mi][ni][3] = __expf(sa[mi][ni][3] - mrow[mi * 2 + 1]); rs[mi * 2 + 1] += sa[mi][ni][3];
            }
        #pragma unroll
        for (int j = 0; j < 4; j++) {
            rs[j] += __shfl_xor_sync(0xffffffffu, rs[j], 1);
            rs[j] += __shfl_xor_sync(0xffffffffu, rs[j], 2);
            lrow[j] = lrow[j] * fj[j] + rs[j];
        }
        #pragma unroll
        for (int mi = 0; mi < 2; mi++)
            #pragma unroll
            for (int ni = 0; ni < 16; ni++) {
                o[mi][ni][0] *= fj[mi * 2];     o[mi][ni][1] *= fj[mi * 2];
                o[mi][ni][2] *= fj[mi * 2 + 1]; o[mi][ni][3] *= fj[mi * 2 + 1];
            }

        #pragma unroll
        for (int ks2 = 0; ks2 < 2; ks2++) {
            unsigned a[2][4];
            #pragma unroll
            for (int mi = 0; mi < 2; mi++) {
                a[mi][0] = pack_h2(sa[mi][2 * ks2][0],     sa[mi][2 * ks2][1]);
                a[mi][1] = pack_h2(sa[mi][2 * ks2][2],     sa[mi][2 * ks2][3]);
                a[mi][2] = pack_h2(sa[mi][2 * ks2 + 1][0], sa[mi][2 * ks2 + 1][1]);
                a[mi][3] = pack_h2(sa[mi][2 * ks2 + 1][2], sa[mi][2 * ks2 + 1][3]);
            }
            #pragma unroll
            for (int nb = 0; nb < 8; nb++) {
                unsigned vf[4];
                LDSM_X4_T(vf[0], vf[1], vf[2], vf[3],
                          vb + vb_lane + (uint32_t)(ks2 * 16 * 272 + nb * 32));
                unsigned b0[2] = { vf[0], vf[1] };
                unsigned b1[2] = { vf[2], vf[3] };
                #pragma unroll
                for (int mi = 0; mi < 2; mi++) {
                    mma_f16(o[mi][nb * 2],     a[mi], b0);
                    mma_f16(o[mi][nb * 2 + 1], a[mi], b1);
                }
            }
        }
    }

    float* Ms = reinterpret_cast<float*>(fsm + FAH_QB);
    float* stats = reinterpret_cast<float*>(fsm + FAH_QB + 128 * 132 * 4);
    __syncthreads();
    if (wc == 1) {
        #pragma unroll
        for (int mi = 0; mi < 2; mi++) {
            int r0 = wr * 32 + mi * 16 + lr;
            #pragma unroll
            for (int ni = 0; ni < 16; ni++) {
                *reinterpret_cast<float2*>(&Ms[r0 * 132 + ni * 8 + 2 * lc]) =
                    make_float2(o[mi][ni][0], o[mi][ni][1]);
                *reinterpret_cast<float2*>(&Ms[(r0 + 8) * 132 + ni * 8 + 2 * lc]) =
                    make_float2(o[mi][ni][2], o[mi][ni][3]);
            }
            if (lc == 0) {
                stats[r0 * 2]           = mrow[mi * 2];
                stats[r0 * 2 + 1]       = lrow[mi * 2];
                stats[(r0 + 8) * 2]     = mrow[mi * 2 + 1];
                stats[(r0 + 8) * 2 + 1] = lrow[mi * 2 + 1];
            }
        }
    }
    __syncthreads();
    if (wc == 0) {
        #pragma unroll
        for (int mi = 0; mi < 2; mi++) {
            #pragma unroll
            for (int half = 0; half < 2; half++) {
                int r0 = wr * 32 + mi * 16 + lr + half * 8;
                int j = mi * 2 + half;
                float m1 = stats[r0 * 2];
                float l1 = stats[r0 * 2 + 1];
                float mm = fmaxf(mrow[j], m1);
                float f0 = __expf(mrow[j] - mm), f1 = __expf(m1 - mm);
                float ll = lrow[j] * f0 + l1 * f1;
                float inv = 1.f / ll;
                int rg = qt * 128 + r0;
                if (rg < N_TOK) {
                    __half* dst = Og + ((size_t)(b * N_TOK + rg)) * C_DIM + h * D_HEAD;
                    #pragma unroll
                    for (int ni = 0; ni < 16; ni++) {
                        float2 o1 = *reinterpret_cast<float2*>(&Ms[r0 * 132 + ni * 8 + 2 * lc]);
                        float v0 = (o[mi][ni][half * 2]     * f0 + o1.x * f1) * inv;
                        float v1 = (o[mi][ni][half * 2 + 1] * f0 + o1.y * f1) * inv;
                        *reinterpret_cast<__half2*>(&dst[ni * 8 + 2 * lc]) =
                            __floats2half2_rn(v0, v1);
                    }
                }
            }
        }
    }
}

// ===================== pre-processing kernels =====================

__global__ void conv_half(const float* __restrict__ in, __half* __restrict__ out, long n4)
{
    long i = (long)blockIdx.x * blockDim.x + threadIdx.x;
    long stride = (long)gridDim.x * blockDim.x;
    for (; i < n4; i += stride) {
        float4 v = reinterpret_cast<const float4*>(in)[i];
        reinterpret_cast<__half2*>(out)[i * 2]     = __floats2half2_rn(v.x, v.y);
        reinterpret_cast<__half2*>(out)[i * 2 + 1] = __floats2half2_rn(v.z, v.w);
    }
}

// RMSNorm q,k over full C, fp16 in/out in place; q pre-scaled by 1/sqrt(D).
__global__ void rmsnorm_qk_h(__half* __restrict__ qkvh,
                             const float* __restrict__ qw, const float* __restrict__ kw)
{
    __half* row = qkvh + (size_t)blockIdx.x * (3 * C_DIM);
    int tid = threadIdx.x;
    const float scale = 0.088388347648318447f;   // 1/sqrt(128)
    float sq = 0.f, sk = 0.f;
    for (int i = tid * 8; i < C_DIM; i += 256 * 8) {
        float4 qr = *reinterpret_cast<const float4*>(row + i);           // 8 halfs
        float4 kr = *reinterpret_cast<const float4*>(row + C_DIM + i);
        const __half2* qh = reinterpret_cast<const __half2*>(&qr);
        const __half2* kh = reinterpret_cast<const __half2*>(&kr);
        #pragma unroll
        for (int j = 0; j < 4; j++) {
            float2 q2 = __half22float2(qh[j]);
            float2 k2 = __half22float2(kh[j]);
            sq += q2.x * q2.x + q2.y * q2.y;
            sk += k2.x * k2.x + k2.y * k2.y;
        }
    }
    #pragma unroll
    for (int o = 16; o; o >>= 1) {
        sq += __shfl_xor_sync(0xffffffffu, sq, o);
        sk += __shfl_xor_sync(0xffffffffu, sk, o);
    }
    __shared__ float s1[8], s2[8];
    int lane = tid & 31, warp = tid >> 5;
    if (lane == 0) { s1[warp] = sq; s2[warp] = sk; }
    __syncthreads();
    if (tid == 0) {
        float a = 0.f, b = 0.f;
        #pragma unroll
        for (int w = 0; w < 8; w++) { a += s1[w]; b += s2[w]; }
        s1[0] = rsqrtf(a / C_DIM + 1e-6f);
        s2[0] = rsqrtf(b / C_DIM + 1e-6f);
    }
    __syncthreads();
    float invq = s1[0] * scale, invk = s2[0];
    for (int i = tid * 8; i < C_DIM; i += 256 * 8) {
        float4 qr = *reinterpret_cast<const float4*>(row + i);
        float4 kr = *reinterpret_cast<const float4*>(row + C_DIM + i);
        __half2* qh = reinterpret_cast<__half2*>(&qr);
        __half2* kh = reinterpret_cast<__half2*>(&kr);
        float4 qo, ko;
        __half2* qoh = reinterpret_cast<__half2*>(&qo);
        __half2* koh = reinterpret_cast<__half2*>(&ko);
        #pragma unroll
        for (int j = 0; j < 4; j++) {
            float2 q2 = __half22float2(qh[j]);
            float2 k2 = __half22float2(kh[j]);
            qoh[j] = __floats2half2_rn(q2.x * invq * qw[i + j * 2], q2.y * invq * qw[i + j * 2 + 1]);
            koh[j] = __floats2half2_rn(k2.x * invk * kw[i + j * 2], k2.y * invk * kw[i + j * 2 + 1]);
        }
        *reinterpret_cast<float4*>(row + i) = qo;
        *reinterpret_cast<float4*>(row + C_DIM + i) = ko;
    }
}

extern "C" void kernel_launch(void* const* d_in, const int* in_sizes, int n_in,
                              void* d_out, int out_size)
{
    const float* x        = (const float*)d_in[0];
    const float* qkv_w    = (const float*)d_in[1];
    const float* qkv_b    = (const float*)d_in[2];
    const float* q_norm_w = (const float*)d_in[3];
    const float* k_norm_w = (const float*)d_in[4];
    const float* proj_w   = (const float*)d_in[5];
    const float* proj_b   = (const float*)d_in[6];
    float* out = (float*)d_out;

    __half *qkvh, *xh, *wqkvh, *wprojh, *atth;
    cudaGetSymbolAddress((void**)&qkvh,   g_qkvh);
    cudaGetSymbolAddress((void**)&xh,     g_xh);
    cudaGetSymbolAddress((void**)&wqkvh,  g_wqkvh);
    cudaGetSymbolAddress((void**)&wprojh, g_wprojh);
    cudaGetSymbolAddress((void**)&atth,   g_atth);

    cudaFuncSetAttribute(hgemm<__half>, cudaFuncAttributeMaxDynamicSharedMemorySize, HG_SMEM);
    cudaFuncSetAttribute(hgemm<float>,  cudaFuncAttributeMaxDynamicSharedMemorySize, HG_SMEM);
    cudaFuncSetAttribute(flash_attn_h, cudaFuncAttributeMaxDynamicSharedMemorySize, FAH_SMEM);

    dim3 blk(256);

    // 0. Convert GEMM operands to fp16
    conv_half<<<2048, 256>>>(x, xh, (long)M_ROWS * C_DIM / 4);
    conv_half<<<2048, 256>>>(qkv_w, wqkvh, (long)C_DIM * 3 * C_DIM / 4);
    conv_half<<<2048, 256>>>(proj_w, wprojh, (long)C_DIM * C_DIM / 4);

    // 1. QKV GEMM (fp16 in, fp16 out): [8200,3200] x [3200,9600] + bias
    {
        int TM = (M_ROWS + 127) / 128;          // 65
        int TN = (3 * C_DIM) / 128;             // 75
        hgemm<__half><<<dim3(TM * TN, 1, 1), blk, HG_SMEM>>>(
            xh, wqkvh, qkv_b, qkvh, M_ROWS, 3 * C_DIM, C_DIM,
            C_DIM, 3 * C_DIM, 3 * C_DIM, TM, TN);
    }

    // 2. RMSNorm q,k in place on fp16 (q pre-scaled)
    rmsnorm_qk_h<<<M_ROWS, blk>>>(qkvh, q_norm_w, k_norm_w);

    // 3-5. Fused flash attention (fp16) -> g_atth
    flash_attn_h<<<dim3(9, 200), blk, FAH_SMEM>>>(qkvh, atth);

    // 6. Proj GEMM (fp16 in, f32 out): [8200,3200] x [3200,3200] + bias -> out
    {
        int TM = (M_ROWS + 127) / 128;          // 65
        int TN = C_DIM / 128;                   // 25
        hgemm<float><<<dim3(TM * TN, 1, 1), blk, HG_SMEM>>>(
            atth, wprojh, proj_b, out, M_ROWS, C_DIM, C_DIM,
            C_DIM, C_DIM, C_DIM, TM, TN);
    }
}

// round 13
// speedup vs baseline: 5.4441x; 1.0151x over previous
#include <cuda_runtime.h>
#include <cuda_fp16.h>
#include <math.h>
#include <stdint.h>

// Problem constants
#define H_HEADS 25
#define B_DIM   8
#define N_TOK   1025
#define C_DIM   3200
#define D_HEAD  128
#define M_ROWS  (B_DIM * N_TOK)   // 8200

// Scratch (device globals)
__device__ __half g_qkvh[(size_t)M_ROWS * 3 * C_DIM];     // fp16 qkv (normed in place)
__device__ __half g_xh[(size_t)M_ROWS * C_DIM];           // x in fp16
__device__ __half g_wqkvh[(size_t)C_DIM * 3 * C_DIM];     // qkv_w in fp16
__device__ __half g_wprojh[(size_t)C_DIM * C_DIM];        // proj_w in fp16
__device__ __half g_atth[(size_t)M_ROWS * C_DIM];         // attention out in fp16

__device__ __forceinline__ void cp16(uint32_t dst, const void* src, int bytes) {
    asm volatile("cp.async.cg.shared.global [%0], [%1], 16, %2;\n"
                 :: "r"(dst), "l"(src), "r"(bytes));
}
__device__ __forceinline__ void cp_commit() { asm volatile("cp.async.commit_group;\n" ::); }
template<int NN>
__device__ __forceinline__ void cp_wait() { asm volatile("cp.async.wait_group %0;\n" :: "n"(NN)); }

__device__ __forceinline__ uint32_t smem_u32(const void* p) {
    return (uint32_t)__cvta_generic_to_shared(p);
}

__device__ __forceinline__ void mma_f16(float (&d)[4], const unsigned (&a)[4], const unsigned (&b)[2]) {
    asm volatile(
        "mma.sync.aligned.m16n8k16.row.col.f32.f16.f16.f32 "
        "{%0,%1,%2,%3}, {%4,%5,%6,%7}, {%8,%9}, {%0,%1,%2,%3};"
        : "+f"(d[0]), "+f"(d[1]), "+f"(d[2]), "+f"(d[3])
        : "r"(a[0]), "r"(a[1]), "r"(a[2]), "r"(a[3]), "r"(b[0]), "r"(b[1]));
}

__device__ __forceinline__ unsigned pack_h2(float a, float b) {
    __half2 h = __floats2half2_rn(a, b);
    return *reinterpret_cast<unsigned*>(&h);
}

#define LDSM_X4(r0, r1, r2, r3, addr) \
    asm volatile("ldmatrix.sync.aligned.m8n8.x4.shared.b16 {%0,%1,%2,%3}, [%4];" \
                 : "=r"(r0), "=r"(r1), "=r"(r2), "=r"(r3) : "r"(addr))
#define LDSM_X4_T(r0, r1, r2, r3, addr) \
    asm volatile("ldmatrix.sync.aligned.m8n8.x4.trans.shared.b16 {%0,%1,%2,%3}, [%4];" \
                 : "=r"(r0), "=r"(r1), "=r"(r2), "=r"(r3) : "r"(addr))

// =====================================================================
// FP16 GEMM, 128x128x64 CTA tile, 2 CTAs/SM, warp tile 64x32 (2x4 grid).
// 3-stage cp.async pipeline (wait 1). Output f32 or fp16 (OutT).
// A smem: [128][72]h (144B rows); B smem: [64][136]h (272B rows).
// =====================================================================
#define HG_AB   (128 * 72 * 2)               // 18432 B
#define HG_BB   (64 * 136 * 2)               // 17408 B
#define HG_STB  (HG_AB + HG_BB)              // 35840 B
#define HG_SMEM (3 * HG_STB)                 // 107520 B

template<typename OutT>
__global__ void __launch_bounds__(256, 2)
hgemm(const __half* __restrict__ A, const __half* __restrict__ B,
      const float* __restrict__ bias, OutT* __restrict__ C,
      int M, int N, int K, long lda, long ldb, long ldc, int TM, int TN)
{
    extern __shared__ __half hsm[];

    int tm, tn;
    {
        const int GM = 16;
        int per = GM * TN;
        int g = blockIdx.x / per, r = blockIdx.x - g * per;
        int rows = TM - g * GM; if (rows > GM) rows = GM;
        tm = g * GM + r % rows;
        tn = r / rows;
    }
    const int bm0 = tm * 128;
    const int bn0 = tn * 128;

    const int tid = threadIdx.x;
    const int lane = tid & 31, warp = tid >> 5;
    const int wm = warp & 1, wn = warp >> 1;      // 2 x 4 warp grid
    const int lr = lane >> 2, lc = lane & 3;

    const uint32_t smbase = smem_u32(hsm);
    const int j8 = lane >> 3, i8 = lane & 7;
    const uint32_t a_lane = (uint32_t)((wm * 64 + (j8 & 1) * 8 + i8) * 144 + (j8 >> 1) * 16);
    const uint32_t b_lane = (uint32_t)(((j8 & 1) * 8 + i8) * 272 + (wn * 32 + (j8 >> 1) * 8) * 2);

    float acc[4][4][4];
    #pragma unroll
    for (int mi = 0; mi < 4; mi++)
        #pragma unroll
        for (int ni = 0; ni < 4; ni++)
            #pragma unroll
            for (int r = 0; r < 4; r++)
                acc[mi][ni][r] = 0.f;

    const int T = K / 64;

    auto load_tiles = [&](int t, int s) {
        int k0 = t * 64;
        uint32_t ab = smbase + (uint32_t)s * HG_STB;
        uint32_t bb = ab + HG_AB;
        // A tile: 128 rows x 8 chunks(16B) -> 4 iters
        #pragma unroll
        for (int i = 0; i < 4; i++) {
            int f = tid + i * 256;
            int row = f >> 3, c = f & 7;
            int gm = bm0 + row;
            const __half* src = A; int bytes = 0;
            if (gm < M) { src = A + (size_t)gm * lda + k0 + c * 8; bytes = 16; }
            cp16(ab + (uint32_t)(row * 144 + c * 16), src, bytes);
        }
        // B tile: 64 rows(k) x 16 chunks -> 4 iters
        #pragma unroll
        for (int i = 0; i < 4; i++) {
            int f = tid + i * 256;
            int kr = f >> 4, nc = f & 15;
            int gn = bn0 + nc * 8;
            const __half* src = B; int bytes = 0;
            if (gn < N) { src = B + (size_t)(k0 + kr) * ldb + gn; bytes = 16; }
            cp16(bb + (uint32_t)(kr * 272 + nc * 16), src, bytes);
        }
    };

    load_tiles(0, 0); cp_commit();
    if (T > 1) load_tiles(1, 1);
    cp_commit();

    for (int t = 0; t < T; t++) {
        if (t + 1 < T) cp_wait<1>(); else cp_wait<0>();
        __syncthreads();
        if (t + 2 < T) { load_tiles(t + 2, (t + 2) % 3); }
        cp_commit();
        uint32_t asb = smbase + (uint32_t)(t % 3) * HG_STB;
        uint32_t bsb = asb + HG_AB;
        #pragma unroll
        for (int ks = 0; ks < 4; ks++) {
            unsigned af[4][4], bf[2][4];
            #pragma unroll
            for (int mi = 0; mi < 4; mi++)
                LDSM_X4(af[mi][0], af[mi][1], af[mi][2], af[mi][3],
                        asb + a_lane + (uint32_t)(mi * 2304 + ks * 32));
            #pragma unroll
            for (int nb = 0; nb < 2; nb++)
                LDSM_X4_T(bf[nb][0], bf[nb][1], bf[nb][2], bf[nb][3],
                          bsb + b_lane + (uint32_t)(nb * 32 + ks * 4352));
            #pragma unroll
            for (int mi = 0; mi < 4; mi++)
                #pragma unroll
                for (int nb = 0; nb < 2; nb++) {
                    unsigned b0[2] = { bf[nb][0], bf[nb][1] };
                    unsigned b1[2] = { bf[nb][2], bf[nb][3] };
                    mma_f16(acc[mi][nb * 2],     af[mi], b0);
                    mma_f16(acc[mi][nb * 2 + 1], af[mi], b1);
                }
        }
    }

    #pragma unroll
    for (int mi = 0; mi < 4; mi++) {
        #pragma unroll
        for (int ni = 0; ni < 4; ni++) {
            int r0 = bm0 + wm * 64 + mi * 16 + lr;
            int c0 = bn0 + wn * 32 + ni * 8 + lc * 2;
            float b0 = 0.f, b1 = 0.f;
            if (bias && c0 < N) { b0 = bias[c0]; b1 = bias[c0 + 1]; }
            #pragma unroll
            for (int rr = 0; rr < 2; rr++) {
                int rw = r0 + rr * 8;
                if (rw < M && c0 < N) {
                    float v0 = acc[mi][ni][rr * 2]     + b0;
                    float v1 = acc[mi][ni][rr * 2 + 1] + b1;
                    if constexpr (sizeof(OutT) == 2) {
                        *reinterpret_cast<__half2*>(
                            reinterpret_cast<__half*>(C) + (size_t)rw * ldc + c0) =
                            __floats2half2_rn(v0, v1);
                    } else {
                        reinterpret_cast<float*>(C)[(size_t)rw * ldc + c0]     = v0;
                        reinterpret_cast<float*>(C)[(size_t)rw * ldc + c0 + 1] = v1;
                    }
                }
            }
        }
    }
}

// =====================================================================
// Fused flash attention, full fp16 datapath (validated R11/R12).
// =====================================================================
#define FAH_QB   (128 * 136 * 2)
#define FAH_KVB  (64 * 136 * 2)
#define FAH_SMEM (FAH_QB + 4 * FAH_KVB + 1024)
#define FA_T     17

__global__ void __launch_bounds__(256, 1)
flash_attn_h(const __half* __restrict__ qkvh, __half* __restrict__ Og)
{
    extern __shared__ char fsm[];
    const uint32_t smb = smem_u32(fsm);
    const int tid = threadIdx.x, w = tid >> 5, lane = tid & 31;
    const int wr = w >> 1, wc = w & 1;
    const int lr = lane >> 2, lc = lane & 3;
    const int j8 = lane >> 3, i8 = lane & 7;
    const int qt = blockIdx.x, bh = blockIdx.y;
    const int b = bh / H_HEADS, h = bh - b * H_HEADS;

    const __half* qbase = qkvh + (size_t)b * N_TOK * (3 * C_DIM) + h * D_HEAD;

    const uint32_t qa_lane = (uint32_t)((wr * 32 + (j8 & 1) * 8 + i8) * 272 + (j8 >> 1) * 16);
    const uint32_t kb_lane = (uint32_t)((wc * 32 + (j8 & 1) * 8 + i8) * 272 + (j8 >> 1) * 16);
    const uint32_t vb_lane = (uint32_t)(((wc * 32 + (j8 & 1) * 8 + i8) * 272) + ((j8 >> 1) * 8) * 2);

    #pragma unroll
    for (int i = 0; i < 8; i++) {
        int id = tid + i * 256;
        int r = id >> 4, c = id & 15;
        int q = qt * 128 + r;
        const __half* src = qbase; int bytes = 0;
        if (q < N_TOK) { src = qbase + (size_t)q * (3 * C_DIM) + c * 8; bytes = 16; }
        cp16(smb + (uint32_t)(r * 272 + c * 16), src, bytes);
    }
    auto load_kv = [&](int t, int s) {
        uint32_t kb = smb + FAH_QB + (uint32_t)s * 2 * FAH_KVB;
        uint32_t vb = kb + FAH_KVB;
        #pragma unroll
        for (int i = 0; i < 4; i++) {
            int id = tid + i * 256;
            int r = id >> 4, c = id & 15;
            int kv = t * 64 + r;
            const __half* srck = qbase; const __half* srcv = qbase; int bytes = 0;
            if (kv < N_TOK) {
                srck = qbase + (size_t)kv * (3 * C_DIM) + C_DIM + c * 8;
                srcv = qbase + (size_t)kv * (3 * C_DIM) + 2 * C_DIM + c * 8;
                bytes = 16;
            }
            cp16(kb + (uint32_t)(r * 272 + c * 16), srck, bytes);
            cp16(vb + (uint32_t)(r * 272 + c * 16), srcv, bytes);
        }
    };
    load_kv(0, 0);
    cp_commit();

    float o[2][16][4];
    #pragma unroll
    for (int mi = 0; mi < 2; mi++)
        #pragma unroll
        for (int ni = 0; ni < 16; ni++)
            #pragma unroll
            for (int r = 0; r < 4; r++) o[mi][ni][r] = 0.f;
    float mrow[4] = {-1e30f, -1e30f, -1e30f, -1e30f};
    float lrow[4] = {0.f, 0.f, 0.f, 0.f};

    for (int t = 0; t < FA_T; t++) {
        int s = t & 1;
        cp_wait<0>();
        __syncthreads();
        if (t + 1 < FA_T) load_kv(t + 1, s ^ 1);
        cp_commit();

        uint32_t kb = smb + FAH_QB + (uint32_t)s * 2 * FAH_KVB;
        uint32_t vb = kb + FAH_KVB;

        float sa[2][4][4];
        #pragma unroll
        for (int mi = 0; mi < 2; mi++)
            #pragma unroll
            for (int ni = 0; ni < 4; ni++)
                #pragma unroll
                for (int r = 0; r < 4; r++) sa[mi][ni][r] = 0.f;

        #pragma unroll
        for (int ks = 0; ks < 8; ks++) {
            unsigned af[2][4], kf[2][4];
            #pragma unroll
            for (int mi = 0; mi < 2; mi++)
                LDSM_X4(af[mi][0], af[mi][1], af[mi][2], af[mi][3],
                        smb + qa_lane + (uint32_t)(mi * 16 * 272 + ks * 32));
            #pragma unroll
            for (int g = 0; g < 2; g++)
                LDSM_X4(kf[g][0], kf[g][1], kf[g][2], kf[g][3],
                        kb + kb_lane + (uint32_t)(g * 16 * 272 + ks * 32));
            #pragma unroll
            for (int mi = 0; mi < 2; mi++)
                #pragma unroll
                for (int g = 0; g < 2; g++) {
                    unsigned b0[2] = { kf[g][0], kf[g][2] };
                    unsigned b1[2] = { kf[g][1], kf[g][3] };
                    mma_f16(sa[mi][g * 2],     af[mi], b0);
                    mma_f16(sa[mi][g * 2 + 1], af[mi], b1);
                }
        }

        if (t == FA_T - 1) {
            #pragma unroll
            for (int ni = 0; ni < 4; ni++) {
                int col = t * 64 + wc * 32 + ni * 8 + 2 * lc;
                if (col >= N_TOK) {
                    #pragma unroll
                    for (int mi = 0; mi < 2; mi++) { sa[mi][ni][0] = -1e30f; sa[mi][ni][2] = -1e30f; }
                }
                if (col + 1 >= N_TOK) {
                    #pragma unroll
                    for (int mi = 0; mi < 2; mi++) { sa[mi][ni][1] = -1e30f; sa[mi][ni][3] = -1e30f; }
                }
            }
        }

        float tm[4] = {-1e30f, -1e30f, -1e30f, -1e30f};
        #pragma unroll
        for (int mi = 0; mi < 2; mi++)
            #pragma unroll
            for (int ni = 0; ni < 4; ni++) {
                tm[mi * 2 + 0] = fmaxf(tm[mi * 2 + 0], fmaxf(sa[mi][ni][0], sa[mi][ni][1]));
                tm[mi * 2 + 1] = fmaxf(tm[mi * 2 + 1], fmaxf(sa[mi][ni][2], sa[mi][ni][3]));
            }
        #pragma unroll
        for (int j = 0; j < 4; j++) {
            tm[j] = fmaxf(tm[j], __shfl_xor_sync(0xffffffffu, tm[j], 1));
            tm[j] = fmaxf(tm[j], __shfl_xor_sync(0xffffffffu, tm[j], 2));
        }
        float fj[4];
        #pragma unroll
        for (int j = 0; j < 4; j++) {
            float mn = fmaxf(mrow[j], tm[j]);
            fj[j] = __expf(mrow[j] - mn);
            mrow[j] = mn;
        }
        float rs[4] = {0.f, 0.f, 0.f, 0.f};
        #pragma unroll
        for (int mi = 0; mi < 2; mi++)
            #pragma unroll
            for (int ni = 0; ni < 4; ni++) {
                sa[mi][ni][0] = __expf(sa[mi][ni][0] - mrow[mi * 2]);     rs[mi * 2] += sa[mi][ni][0];
                sa[mi][ni][1] = __expf(sa[mi][ni][1] - mrow[mi * 2]);     rs[mi * 2] += sa[mi][ni][1];
                sa[mi][ni][2] = __expf(sa[mi][ni][2] - mrow[mi * 2 + 1]); rs[mi * 2 + 1] += sa[mi][ni][2];
                sa[mi][ni][3] = __expf(sa[mi][ni][3] - mrow[mi * 2 + 1]); rs[mi * 2 + 1] += sa[mi][ni][3];
            }
        #pragma unroll
        for (int j = 0; j < 4; j++) {
            rs[j] += __shfl_xor_sync(0xffffffffu, rs[j], 1);
            rs[j] += __shfl_xor_sync(0xffffffffu, rs[j], 2);
            lrow[j] = lrow[j] * fj[j] + rs[j];
        }
        #pragma unroll
        for (int mi = 0; mi < 2; mi++)
            #pragma unroll
            for (int ni = 0; ni < 16; ni++) {
                o[mi][ni][0] *= fj[mi * 2];     o[mi][ni][1] *= fj[mi * 2];
                o[mi][ni][2] *= fj[mi * 2 + 1]; o[mi][ni][3] *= fj[mi * 2 + 1];
            }

        #pragma unroll
        for (int ks2 = 0; ks2 < 2; ks2++) {
            unsigned a[2][4];
            #pragma unroll
            for (int mi = 0; mi < 2; mi++) {
                a[mi][0] = pack_h2(sa[mi][2 * ks2][0],     sa[mi][2 * ks2][1]);
                a[mi][1] = pack_h2(sa[mi][2 * ks2][2],     sa[mi][2 * ks2][3]);
                a[mi][2] = pack_h2(sa[mi][2 * ks2 + 1][0], sa[mi][2 * ks2 + 1][1]);
                a[mi][3] = pack_h2(sa[mi][2 * ks2 + 1][2], sa[mi][2 * ks2 + 1][3]);
            }
            #pragma unroll
            for (int nb = 0; nb < 8; nb++) {
                unsigned vf[4];
                LDSM_X4_T(vf[0], vf[1], vf[2], vf[3],
                          vb + vb_lane + (uint32_t)(ks2 * 16 * 272 + nb * 32));
                unsigned b0[2] = { vf[0], vf[1] };
                unsigned b1[2] = { vf[2], vf[3] };
                #pragma unroll
                for (int mi = 0; mi < 2; mi++) {
                    mma_f16(o[mi][nb * 2],     a[mi], b0);
                    mma_f16(o[mi][nb * 2 + 1], a[mi], b1);
                }
            }
        }
    }

    float* Ms = reinterpret_cast<float*>(fsm + FAH_QB);
    float* stats = reinterpret_cast<float*>(fsm + FAH_QB + 128 * 132 * 4);
    __syncthreads();
    if (wc == 1) {
        #pragma unroll
        for (int mi = 0; mi < 2; mi++) {
            int r0 = wr * 32 + mi * 16 + lr;
            #pragma unroll
            for (int ni = 0; ni < 16; ni++) {
                *reinterpret_cast<float2*>(&Ms[r0 * 132 + ni * 8 + 2 * lc]) =
                    make_float2(o[mi][ni][0], o[mi][ni][1]);
                *reinterpret_cast<float2*>(&Ms[(r0 + 8) * 132 + ni * 8 + 2 * lc]) =
                    make_float2(o[mi][ni][2], o[mi][ni][3]);
            }
            if (lc == 0) {
                stats[r0 * 2]           = mrow[mi * 2];
                stats[r0 * 2 + 1]       = lrow[mi * 2];
                stats[(r0 + 8) * 2]     = mrow[mi * 2 + 1];
                stats[(r0 + 8) * 2 + 1] = lrow[mi * 2 + 1];
            }
        }
    }
    __syncthreads();
    if (wc == 0) {
        #pragma unroll
        for (int mi = 0; mi < 2; mi++) {
            #pragma unroll
            for (int half = 0; half < 2; half++) {
                int r0 = wr * 32 + mi * 16 + lr + half * 8;
                int j = mi * 2 + half;
                float m1 = stats[r0 * 2];
                float l1 = stats[r0 * 2 + 1];
                float mm = fmaxf(mrow[j], m1);
                float f0 = __expf(mrow[j] - mm), f1 = __expf(m1 - mm);
                float ll = lrow[j] * f0 + l1 * f1;
                float inv = 1.f / ll;
                int rg = qt * 128 + r0;
                if (rg < N_TOK) {
                    __half* dst = Og + ((size_t)(b * N_TOK + rg)) * C_DIM + h * D_HEAD;
                    #pragma unroll
                    for (int ni = 0; ni < 16; ni++) {
                        float2 o1 = *reinterpret_cast<float2*>(&Ms[r0 * 132 + ni * 8 + 2 * lc]);
                        float v0 = (o[mi][ni][half * 2]     * f0 + o1.x * f1) * inv;
                        float v1 = (o[mi][ni][half * 2 + 1] * f0 + o1.y * f1) * inv;
                        *reinterpret_cast<__half2*>(&dst[ni * 8 + 2 * lc]) =
                            __floats2half2_rn(v0, v1);
                    }
                }
            }
        }
    }
}

// ===================== pre-processing kernels =====================

__global__ void conv_half(const float* __restrict__ in, __half* __restrict__ out, long n4)
{
    long i = (long)blockIdx.x * blockDim.x + threadIdx.x;
    long stride = (long)gridDim.x * blockDim.x;
    for (; i < n4; i += stride) {
        float4 v = reinterpret_cast<const float4*>(in)[i];
        reinterpret_cast<__half2*>(out)[i * 2]     = __floats2half2_rn(v.x, v.y);
        reinterpret_cast<__half2*>(out)[i * 2 + 1] = __floats2half2_rn(v.z, v.w);
    }
}

// RMSNorm q,k over full C, fp16 in/out in place; q pre-scaled by 1/sqrt(D).
__global__ void rmsnorm_qk_h(__half* __restrict__ qkvh,
                             const float* __restrict__ qw, const float* __restrict__ kw)
{
    __half* row = qkvh + (size_t)blockIdx.x * (3 * C_DIM);
    int tid = threadIdx.x;
    const float scale = 0.088388347648318447f;   // 1/sqrt(128)
    float sq = 0.f, sk = 0.f;
    for (int i = tid * 8; i < C_DIM; i += 256 * 8) {
        float4 qr = *reinterpret_cast<const float4*>(row + i);           // 8 halfs
        float4 kr = *reinterpret_cast<const float4*>(row + C_DIM + i);
        const __half2* qh = reinterpret_cast<const __half2*>(&qr);
        const __half2* kh = reinterpret_cast<const __half2*>(&kr);
        #pragma unroll
        for (int j = 0; j < 4; j++) {
            float2 q2 = __half22float2(qh[j]);
            float2 k2 = __half22float2(kh[j]);
            sq += q2.x * q2.x + q2.y * q2.y;
            sk += k2.x * k2.x + k2.y * k2.y;
        }
    }
    #pragma unroll
    for (int o = 16; o; o >>= 1) {
        sq += __shfl_xor_sync(0xffffffffu, sq, o);
        sk += __shfl_xor_sync(0xffffffffu, sk, o);
    }
    __shared__ float s1[8], s2[8];
    int lane = tid & 31, warp = tid >> 5;
    if (lane == 0) { s1[warp] = sq; s2[warp] = sk; }
    __syncthreads();
    if (tid == 0) {
        float a = 0.f, b = 0.f;
        #pragma unroll
        for (int w = 0; w < 8; w++) { a += s1[w]; b += s2[w]; }
        s1[0] = rsqrtf(a / C_DIM + 1e-6f);
        s2[0] = rsqrtf(b / C_DIM + 1e-6f);
    }
    __syncthreads();
    float invq = s1[0] * scale, invk = s2[0];
    for (int i = tid * 8; i < C_DIM; i += 256 * 8) {
        float4 qr = *reinterpret_cast<const float4*>(row + i);
        float4 kr = *reinterpret_cast<const float4*>(row + C_DIM + i);
        __half2* qh = reinterpret_cast<__half2*>(&qr);
        __half2* kh = reinterpret_cast<__half2*>(&kr);
        float4 qo, ko;
        __half2* qoh = reinterpret_cast<__half2*>(&qo);
        __half2* koh = reinterpret_cast<__half2*>(&ko);
        #pragma unroll
        for (int j = 0; j < 4; j++) {
            float2 q2 = __half22float2(qh[j]);
            float2 k2 = __half22float2(kh[j]);
            qoh[j] = __floats2half2_rn(q2.x * invq * qw[i + j * 2], q2.y * invq * qw[i + j * 2 + 1]);
            koh[j] = __floats2half2_rn(k2.x * invk * kw[i + j * 2], k2.y * invk * kw[i + j * 2 + 1]);
        }
        *reinterpret_cast<float4*>(row + i) = qo;
        *reinterpret_cast<float4*>(row + C_DIM + i) = ko;
    }
}

extern "C" void kernel_launch(void* const* d_in, const int* in_sizes, int n_in,
                              void* d_out, int out_size)
{
    const float* x        = (const float*)d_in[0];
    const float* qkv_w    = (const float*)d_in[1];
    const float* qkv_b    = (const float*)d_in[2];
    const float* q_norm_w = (const float*)d_in[3];
    const float* k_norm_w = (const float*)d_in[4];
    const float* proj_w   = (const float*)d_in[5];
    const float* proj_b   = (const float*)d_in[6];
    float* out = (float*)d_out;

    __half *qkvh, *xh, *wqkvh, *wprojh, *atth;
    cudaGetSymbolAddress((void**)&qkvh,   g_qkvh);
    cudaGetSymbolAddress((void**)&xh,     g_xh);
    cudaGetSymbolAddress((void**)&wqkvh,  g_wqkvh);
    cudaGetSymbolAddress((void**)&wprojh, g_wprojh);
    cudaGetSymbolAddress((void**)&atth,   g_atth);

    cudaFuncSetAttribute(hgemm<__half>, cudaFuncAttributeMaxDynamicSharedMemorySize, HG_SMEM);
    cudaFuncSetAttribute(hgemm<float>,  cudaFuncAttributeMaxDynamicSharedMemorySize, HG_SMEM);
    cudaFuncSetAttribute(flash_attn_h, cudaFuncAttributeMaxDynamicSharedMemorySize, FAH_SMEM);

    dim3 blk(256);

    // 0. Convert GEMM operands to fp16
    conv_half<<<2048, 256>>>(x, xh, (long)M_ROWS * C_DIM / 4);
    conv_half<<<2048, 256>>>(qkv_w, wqkvh, (long)C_DIM * 3 * C_DIM / 4);
    conv_half<<<2048, 256>>>(proj_w, wprojh, (long)C_DIM * C_DIM / 4);

    // 1. QKV GEMM (fp16 in, fp16 out): [8200,3200] x [3200,9600] + bias
    {
        int TM = (M_ROWS + 127) / 128;          // 65
        int TN = (3 * C_DIM) / 128;             // 75
        hgemm<__half><<<dim3(TM * TN, 1, 1), blk, HG_SMEM>>>(
            xh, wqkvh, qkv_b, qkvh, M_ROWS, 3 * C_DIM, C_DIM,
            C_DIM, 3 * C_DIM, 3 * C_DIM, TM, TN);
    }

    // 2. RMSNorm q,k in place on fp16 (q pre-scaled)
    rmsnorm_qk_h<<<M_ROWS, blk>>>(qkvh, q_norm_w, k_norm_w);

    // 3-5. Fused flash attention (fp16) -> g_atth
    flash_attn_h<<<dim3(9, 200), blk, FAH_SMEM>>>(qkvh, atth);

    // 6. Proj GEMM (fp16 in, f32 out): [8200,3200] x [3200,3200] + bias -> out
    {
        int TM = (M_ROWS + 127) / 128;          // 65
        int TN = C_DIM / 128;                   // 25
        hgemm<float><<<dim3(TM * TN, 1, 1), blk, HG_SMEM>>>(
            atth, wprojh, proj_b, out, M_ROWS, C_DIM, C_DIM,
            C_DIM, C_DIM, C_DIM, TM, TN);
    }
}

// round 14
// speedup vs baseline: 5.6346x; 1.0350x over previous
#include <cuda_runtime.h>
#include <cuda_fp16.h>
#include <math.h>
#include <stdint.h>

// Problem constants
#define H_HEADS 25
#define B_DIM   8
#define N_TOK   1025
#define C_DIM   3200
#define D_HEAD  128
#define M_ROWS  (B_DIM * N_TOK)   // 8200

// Scratch (device globals)
__device__ __half g_qkvh[(size_t)M_ROWS * 3 * C_DIM];     // fp16 qkv (normed in place)
__device__ __half g_xh[(size_t)M_ROWS * C_DIM];           // x in fp16
__device__ __half g_wqkvh[(size_t)C_DIM * 3 * C_DIM];     // qkv_w in fp16
__device__ __half g_wprojh[(size_t)C_DIM * C_DIM];        // proj_w in fp16
__device__ __half g_atth[(size_t)M_ROWS * C_DIM];         // attention out in fp16

__device__ __forceinline__ void cp16(uint32_t dst, const void* src, int bytes) {
    asm volatile("cp.async.cg.shared.global [%0], [%1], 16, %2;\n"
                 :: "r"(dst), "l"(src), "r"(bytes));
}
__device__ __forceinline__ void cp_commit() { asm volatile("cp.async.commit_group;\n" ::); }
template<int NN>
__device__ __forceinline__ void cp_wait() { asm volatile("cp.async.wait_group %0;\n" :: "n"(NN)); }

__device__ __forceinline__ uint32_t smem_u32(const void* p) {
    return (uint32_t)__cvta_generic_to_shared(p);
}

__device__ __forceinline__ void mma_f16(float (&d)[4], const unsigned (&a)[4], const unsigned (&b)[2]) {
    asm volatile(
        "mma.sync.aligned.m16n8k16.row.col.f32.f16.f16.f32 "
        "{%0,%1,%2,%3}, {%4,%5,%6,%7}, {%8,%9}, {%0,%1,%2,%3};"
        : "+f"(d[0]), "+f"(d[1]), "+f"(d[2]), "+f"(d[3])
        : "r"(a[0]), "r"(a[1]), "r"(a[2]), "r"(a[3]), "r"(b[0]), "r"(b[1]));
}

__device__ __forceinline__ unsigned pack_h2(float a, float b) {
    __half2 h = __floats2half2_rn(a, b);
    return *reinterpret_cast<unsigned*>(&h);
}

#define LDSM_X4(r0, r1, r2, r3, addr) \
    asm volatile("ldmatrix.sync.aligned.m8n8.x4.shared.b16 {%0,%1,%2,%3}, [%4];" \
                 : "=r"(r0), "=r"(r1), "=r"(r2), "=r"(r3) : "r"(addr))
#define LDSM_X4_T(r0, r1, r2, r3, addr) \
    asm volatile("ldmatrix.sync.aligned.m8n8.x4.trans.shared.b16 {%0,%1,%2,%3}, [%4];" \
                 : "=r"(r0), "=r"(r1), "=r"(r2), "=r"(r3) : "r"(addr))

// =====================================================================
// FP16 GEMM, 128x128x64 CTA tile, 2 CTAs/SM, warp tile 64x32 (2x4 grid).
// 3-stage cp.async pipeline (wait 1). Hoisted per-thread load pointers.
// A smem: [128][72]h (144B rows); B smem: [64][136]h (272B rows).
// =====================================================================
#define HG_AB   (128 * 72 * 2)               // 18432 B
#define HG_BB   (64 * 136 * 2)               // 17408 B
#define HG_STB  (HG_AB + HG_BB)              // 35840 B
#define HG_SMEM (3 * HG_STB)                 // 107520 B

template<typename OutT>
__global__ void __launch_bounds__(256, 2)
hgemm(const __half* __restrict__ A, const __half* __restrict__ B,
      const float* __restrict__ bias, OutT* __restrict__ C,
      int M, int N, int K, long lda, long ldb, long ldc, int TM, int TN)
{
    extern __shared__ __half hsm[];

    int tm, tn;
    {
        const int GM = 16;
        int per = GM * TN;
        int g = blockIdx.x / per, r = blockIdx.x - g * per;
        int rows = TM - g * GM; if (rows > GM) rows = GM;
        tm = g * GM + r % rows;
        tn = r / rows;
    }
    const int bm0 = tm * 128;
    const int bn0 = tn * 128;

    const int tid = threadIdx.x;
    const int lane = tid & 31, warp = tid >> 5;
    const int wm = warp & 1, wn = warp >> 1;      // 2 x 4 warp grid
    const int lr = lane >> 2, lc = lane & 3;

    const uint32_t smbase = smem_u32(hsm);
    const int j8 = lane >> 3, i8 = lane & 7;
    const uint32_t a_lane = (uint32_t)((wm * 64 + (j8 & 1) * 8 + i8) * 144 + (j8 >> 1) * 16);
    const uint32_t b_lane = (uint32_t)(((j8 & 1) * 8 + i8) * 272 + (wn * 32 + (j8 >> 1) * 8) * 2);

    // ---- hoisted per-thread load descriptors ----
    const __half* aptr[4];  uint32_t adst[4];  int abytes[4];
    const __half* bptr[4];  uint32_t bdst[4];  int bbytes[4];
    {
        #pragma unroll
        for (int i = 0; i < 4; i++) {
            int f = tid + i * 256;
            int row = f >> 3, c = f & 7;
            int gm = bm0 + row;
            abytes[i] = (gm < M) ? 16 : 0;
            aptr[i] = A + (size_t)(gm < M ? gm : 0) * lda + c * 8;
            adst[i] = (uint32_t)(row * 144 + c * 16);
        }
        #pragma unroll
        for (int i = 0; i < 4; i++) {
            int f = tid + i * 256;
            int kr = f >> 4, nc = f & 15;
            int gn = bn0 + nc * 8;
            bbytes[i] = (gn < N) ? 16 : 0;
            bptr[i] = B + (size_t)kr * ldb + (gn < N ? gn : 0);
            bdst[i] = (uint32_t)(kr * 272 + nc * 16);
        }
    }
    const long bstep = 64 * ldb;

    float acc[4][4][4];
    #pragma unroll
    for (int mi = 0; mi < 4; mi++)
        #pragma unroll
        for (int ni = 0; ni < 4; ni++)
            #pragma unroll
            for (int r = 0; r < 4; r++)
                acc[mi][ni][r] = 0.f;

    const int T = K / 64;

    auto load_tiles = [&](int t, int s) {
        uint32_t sb = smbase + (uint32_t)s * HG_STB;
        long ka = (long)t * 64;
        long kb = (long)t * bstep;
        #pragma unroll
        for (int i = 0; i < 4; i++)
            cp16(sb + adst[i], aptr[i] + ka, abytes[i]);
        uint32_t sbb = sb + HG_AB;
        #pragma unroll
        for (int i = 0; i < 4; i++)
            cp16(sbb + bdst[i], bptr[i] + kb, bbytes[i]);
    };

    load_tiles(0, 0); cp_commit();
    if (T > 1) load_tiles(1, 1);
    cp_commit();

    int scur = 0, snext = 2;
    for (int t = 0; t < T; t++) {
        if (t + 1 < T) cp_wait<1>(); else cp_wait<0>();
        __syncthreads();
        if (t + 2 < T) { load_tiles(t + 2, snext); }
        cp_commit();
        uint32_t asb = smbase + (uint32_t)scur * HG_STB;
        uint32_t bsb = asb + HG_AB;
        if (++scur == 3) scur = 0;
        if (++snext == 3) snext = 0;
        uint32_t abase = asb + a_lane;
        uint32_t bbase = bsb + b_lane;
        #pragma unroll
        for (int ks = 0; ks < 4; ks++) {
            unsigned af[4][4], bf[2][4];
            #pragma unroll
            for (int mi = 0; mi < 4; mi++)
                LDSM_X4(af[mi][0], af[mi][1], af[mi][2], af[mi][3],
                        abase + (uint32_t)(mi * 2304 + ks * 32));
            #pragma unroll
            for (int nb = 0; nb < 2; nb++)
                LDSM_X4_T(bf[nb][0], bf[nb][1], bf[nb][2], bf[nb][3],
                          bbase + (uint32_t)(nb * 32 + ks * 4352));
            #pragma unroll
            for (int mi = 0; mi < 4; mi++)
                #pragma unroll
                for (int nb = 0; nb < 2; nb++) {
                    unsigned b0[2] = { bf[nb][0], bf[nb][1] };
                    unsigned b1[2] = { bf[nb][2], bf[nb][3] };
                    mma_f16(acc[mi][nb * 2],     af[mi], b0);
                    mma_f16(acc[mi][nb * 2 + 1], af[mi], b1);
                }
        }
    }

    #pragma unroll
    for (int mi = 0; mi < 4; mi++) {
        #pragma unroll
        for (int ni = 0; ni < 4; ni++) {
            int r0 = bm0 + wm * 64 + mi * 16 + lr;
            int c0 = bn0 + wn * 32 + ni * 8 + lc * 2;
            float b0 = 0.f, b1 = 0.f;
            if (bias && c0 < N) { b0 = bias[c0]; b1 = bias[c0 + 1]; }
            #pragma unroll
            for (int rr = 0; rr < 2; rr++) {
                int rw = r0 + rr * 8;
                if (rw < M && c0 < N) {
                    float v0 = acc[mi][ni][rr * 2]     + b0;
                    float v1 = acc[mi][ni][rr * 2 + 1] + b1;
                    if constexpr (sizeof(OutT) == 2) {
                        *reinterpret_cast<__half2*>(
                            reinterpret_cast<__half*>(C) + (size_t)rw * ldc + c0) =
                            __floats2half2_rn(v0, v1);
                    } else {
                        reinterpret_cast<float*>(C)[(size_t)rw * ldc + c0]     = v0;
                        reinterpret_cast<float*>(C)[(size_t)rw * ldc + c0 + 1] = v1;
                    }
                }
            }
        }
    }
}

// =====================================================================
// Fused flash attention, full fp16 datapath; hoisted KV load pointers.
// =====================================================================
#define FAH_QB   (128 * 136 * 2)
#define FAH_KVB  (64 * 136 * 2)
#define FAH_SMEM (FAH_QB + 4 * FAH_KVB + 1024)
#define FA_T     17

__global__ void __launch_bounds__(256, 1)
flash_attn_h(const __half* __restrict__ qkvh, __half* __restrict__ Og)
{
    extern __shared__ char fsm[];
    const uint32_t smb = smem_u32(fsm);
    const int tid = threadIdx.x, w = tid >> 5, lane = tid & 31;
    const int wr = w >> 1, wc = w & 1;
    const int lr = lane >> 2, lc = lane & 3;
    const int j8 = lane >> 3, i8 = lane & 7;
    const int qt = blockIdx.x, bh = blockIdx.y;
    const int b = bh / H_HEADS, h = bh - b * H_HEADS;

    const __half* qbase = qkvh + (size_t)b * N_TOK * (3 * C_DIM) + h * D_HEAD;

    const uint32_t qa_lane = (uint32_t)((wr * 32 + (j8 & 1) * 8 + i8) * 272 + (j8 >> 1) * 16);
    const uint32_t kb_lane = (uint32_t)((wc * 32 + (j8 & 1) * 8 + i8) * 272 + (j8 >> 1) * 16);
    const uint32_t vb_lane = (uint32_t)(((wc * 32 + (j8 & 1) * 8 + i8) * 272) + ((j8 >> 1) * 8) * 2);

    // ---- load Q tile (once) ----
    #pragma unroll
    for (int i = 0; i < 8; i++) {
        int id = tid + i * 256;
        int r = id >> 4, c = id & 15;
        int q = qt * 128 + r;
        const __half* src = qbase; int bytes = 0;
        if (q < N_TOK) { src = qbase + (size_t)q * (3 * C_DIM) + c * 8; bytes = 16; }
        cp16(smb + (uint32_t)(r * 272 + c * 16), src, bytes);
    }

    // ---- hoisted per-thread KV load descriptors (4 chunks/thread) ----
    int kv_r[4];
    const __half* kv_ksrc[4];
    const __half* kv_vsrc[4];
    uint32_t kv_dst[4];
    #pragma unroll
    for (int i = 0; i < 4; i++) {
        int id = tid + i * 256;
        int r = id >> 4, c = id & 15;
        kv_r[i] = r;
        kv_ksrc[i] = qbase + (size_t)r * (3 * C_DIM) + C_DIM + c * 8;
        kv_vsrc[i] = kv_ksrc[i] + C_DIM;
        kv_dst[i] = (uint32_t)(r * 272 + c * 16);
    }
    const long kvstep = (long)64 * (3 * C_DIM);

    auto load_kv = [&](int t, int s) {
        uint32_t kb = smb + FAH_QB + (uint32_t)s * 2 * FAH_KVB;
        uint32_t vb = kb + FAH_KVB;
        long off = (long)t * kvstep;
        int base = t * 64;
        #pragma unroll
        for (int i = 0; i < 4; i++) {
            int bytes = (base + kv_r[i] < N_TOK) ? 16 : 0;
            cp16(kb + kv_dst[i], kv_ksrc[i] + off, bytes);
            cp16(vb + kv_dst[i], kv_vsrc[i] + off, bytes);
        }
    };
    load_kv(0, 0);
    cp_commit();

    float o[2][16][4];
    #pragma unroll
    for (int mi = 0; mi < 2; mi++)
        #pragma unroll
        for (int ni = 0; ni < 16; ni++)
            #pragma unroll
            for (int r = 0; r < 4; r++) o[mi][ni][r] = 0.f;
    float mrow[4] = {-1e30f, -1e30f, -1e30f, -1e30f};
    float lrow[4] = {0.f, 0.f, 0.f, 0.f};

    for (int t = 0; t < FA_T; t++) {
        int s = t & 1;
        cp_wait<0>();
        __syncthreads();
        if (t + 1 < FA_T) load_kv(t + 1, s ^ 1);
        cp_commit();

        uint32_t kb = smb + FAH_QB + (uint32_t)s * 2 * FAH_KVB;
        uint32_t vb = kb + FAH_KVB;

        float sa[2][4][4];
        #pragma unroll
        for (int mi = 0; mi < 2; mi++)
            #pragma unroll
            for (int ni = 0; ni < 4; ni++)
                #pragma unroll
                for (int r = 0; r < 4; r++) sa[mi][ni][r] = 0.f;

        uint32_t qb0 = smb + qa_lane;
        uint32_t kb0 = kb + kb_lane;
        #pragma unroll
        for (int ks = 0; ks < 8; ks++) {
            unsigned af[2][4], kf[2][4];
            #pragma unroll
            for (int mi = 0; mi < 2; mi++)
                LDSM_X4(af[mi][0], af[mi][1], af[mi][2], af[mi][3],
                        qb0 + (uint32_t)(mi * 16 * 272 + ks * 32));
            #pragma unroll
            for (int g = 0; g < 2; g++)
                LDSM_X4(kf[g][0], kf[g][1], kf[g][2], kf[g][3],
                        kb0 + (uint32_t)(g * 16 * 272 + ks * 32));
            #pragma unroll
            for (int mi = 0; mi < 2; mi++)
                #pragma unroll
                for (int g = 0; g < 2; g++) {
                    unsigned b0[2] = { kf[g][0], kf[g][2] };
                    unsigned b1[2] = { kf[g][1], kf[g][3] };
                    mma_f16(sa[mi][g * 2],     af[mi], b0);
                    mma_f16(sa[mi][g * 2 + 1], af[mi], b1);
                }
        }

        if (t == FA_T - 1) {
            #pragma unroll
            for (int ni = 0; ni < 4; ni++) {
                int col = t * 64 + wc * 32 + ni * 8 + 2 * lc;
                if (col >= N_TOK) {
                    #pragma unroll
                    for (int mi = 0; mi < 2; mi++) { sa[mi][ni][0] = -1e30f; sa[mi][ni][2] = -1e30f; }
                }
                if (col + 1 >= N_TOK) {
                    #pragma unroll
                    for (int mi = 0; mi < 2; mi++) { sa[mi][ni][1] = -1e30f; sa[mi][ni][3] = -1e30f; }
                }
            }
        }

        float tm[4] = {-1e30f, -1e30f, -1e30f, -1e30f};
        #pragma unroll
        for (int mi = 0; mi < 2; mi++)
            #pragma unroll
            for (int ni = 0; ni < 4; ni++) {
                tm[mi * 2 + 0] = fmaxf(tm[mi * 2 + 0], fmaxf(sa[mi][ni][0], sa[mi][ni][1]));
                tm[mi * 2 + 1] = fmaxf(tm[mi * 2 + 1], fmaxf(sa[mi][ni][2], sa[mi][ni][3]));
            }
        #pragma unroll
        for (int j = 0; j < 4; j++) {
            tm[j] = fmaxf(tm[j], __shfl_xor_sync(0xffffffffu, tm[j], 1));
            tm[j] = fmaxf(tm[j], __shfl_xor_sync(0xffffffffu, tm[j], 2));
        }
        float fj[4];
        #pragma unroll
        for (int j = 0; j < 4; j++) {
            float mn = fmaxf(mrow[j], tm[j]);
            fj[j] = __expf(mrow[j] - mn);
            mrow[j] = mn;
        }
        float rs[4] = {0.f, 0.f, 0.f, 0.f};
        #pragma unroll
        for (int mi = 0; mi < 2; mi++)
            #pragma unroll
            for (int ni = 0; ni < 4; ni++) {
                sa[mi][ni][0] = __expf(sa[mi][ni][0] - mrow[mi * 2]);     rs[mi * 2] += sa[mi][ni][0];
                sa[mi][ni][1] = __expf(sa[mi][ni][1] - mrow[mi * 2]);     rs[mi * 2] += sa[mi][ni][1];
                sa[mi][ni][2] = __expf(sa[mi][ni][2] - mrow[mi * 2 + 1]); rs[mi * 2 + 1] += sa[mi][ni][2];
                sa[mi][ni][3] = __expf(sa[mi][ni][3] - mrow[mi * 2 + 1]); rs[mi * 2 + 1] += sa[mi][ni][3];
            }
        #pragma unroll
        for (int j = 0; j < 4; j++) {
            rs[j] += __shfl_xor_sync(0xffffffffu, rs[j], 1);
            rs[j] += __shfl_xor_sync(0xffffffffu, rs[j], 2);
            lrow[j] = lrow[j] * fj[j] + rs[j];
        }
        #pragma unroll
        for (int mi = 0; mi < 2; mi++)
            #pragma unroll
            for (int ni = 0; ni < 16; ni++) {
                o[mi][ni][0] *= fj[mi * 2];     o[mi][ni][1] *= fj[mi * 2];
                o[mi][ni][2] *= fj[mi * 2 + 1]; o[mi][ni][3] *= fj[mi * 2 + 1];
            }

        uint32_t vb0 = vb + vb_lane;
        #pragma unroll
        for (int ks2 = 0; ks2 < 2; ks2++) {
            unsigned a[2][4];
            #pragma unroll
            for (int mi = 0; mi < 2; mi++) {
                a[mi][0] = pack_h2(sa[mi][2 * ks2][0],     sa[mi][2 * ks2][1]);
                a[mi][1] = pack_h2(sa[mi][2 * ks2][2],     sa[mi][2 * ks2][3]);
                a[mi][2] = pack_h2(sa[mi][2 * ks2 + 1][0], sa[mi][2 * ks2 + 1][1]);
                a[mi][3] = pack_h2(sa[mi][2 * ks2 + 1][2], sa[mi][2 * ks2 + 1][3]);
            }
            #pragma unroll
            for (int nb = 0; nb < 8; nb++) {
                unsigned vf[4];
                LDSM_X4_T(vf[0], vf[1], vf[2], vf[3],
                          vb0 + (uint32_t)(ks2 * 16 * 272 + nb * 32));
                unsigned b0[2] = { vf[0], vf[1] };
                unsigned b1[2] = { vf[2], vf[3] };
                #pragma unroll
                for (int mi = 0; mi < 2; mi++) {
                    mma_f16(o[mi][nb * 2],     a[mi], b0);
                    mma_f16(o[mi][nb * 2 + 1], a[mi], b1);
                }
            }
        }
    }

    float* Ms = reinterpret_cast<float*>(fsm + FAH_QB);
    float* stats = reinterpret_cast<float*>(fsm + FAH_QB + 128 * 132 * 4);
    __syncthreads();
    if (wc == 1) {
        #pragma unroll
        for (int mi = 0; mi < 2; mi++) {
            int r0 = wr * 32 + mi * 16 + lr;
            #pragma unroll
            for (int ni = 0; ni < 16; ni++) {
                *reinterpret_cast<float2*>(&Ms[r0 * 132 + ni * 8 + 2 * lc]) =
                    make_float2(o[mi][ni][0], o[mi][ni][1]);
                *reinterpret_cast<float2*>(&Ms[(r0 + 8) * 132 + ni * 8 + 2 * lc]) =
                    make_float2(o[mi][ni][2], o[mi][ni][3]);
            }
            if (lc == 0) {
                stats[r0 * 2]           = mrow[mi * 2];
                stats[r0 * 2 + 1]       = lrow[mi * 2];
                stats[(r0 + 8) * 2]     = mrow[mi * 2 + 1];
                stats[(r0 + 8) * 2 + 1] = lrow[mi * 2 + 1];
            }
        }
    }
    __syncthreads();
    if (wc == 0) {
        #pragma unroll
        for (int mi = 0; mi < 2; mi++) {
            #pragma unroll
            for (int half = 0; half < 2; half++) {
                int r0 = wr * 32 + mi * 16 + lr + half * 8;
                int j = mi * 2 + half;
                float m1 = stats[r0 * 2];
                float l1 = stats[r0 * 2 + 1];
                float mm = fmaxf(mrow[j], m1);
                float f0 = __expf(mrow[j] - mm), f1 = __expf(m1 - mm);
                float ll = lrow[j] * f0 + l1 * f1;
                float inv = 1.f / ll;
                int rg = qt * 128 + r0;
                if (rg < N_TOK) {
                    __half* dst = Og + ((size_t)(b * N_TOK + rg)) * C_DIM + h * D_HEAD;
                    #pragma unroll
                    for (int ni = 0; ni < 16; ni++) {
                        float2 o1 = *reinterpret_cast<float2*>(&Ms[r0 * 132 + ni * 8 + 2 * lc]);
                        float v0 = (o[mi][ni][half * 2]     * f0 + o1.x * f1) * inv;
                        float v1 = (o[mi][ni][half * 2 + 1] * f0 + o1.y * f1) * inv;
                        *reinterpret_cast<__half2*>(&dst[ni * 8 + 2 * lc]) =
                            __floats2half2_rn(v0, v1);
                    }
                }
            }
        }
    }
}

// ===================== pre-processing kernels =====================

__global__ void conv_half(const float* __restrict__ in, __half* __restrict__ out, long n4)
{
    long i = (long)blockIdx.x * blockDim.x + threadIdx.x;
    long stride = (long)gridDim.x * blockDim.x;
    for (; i < n4; i += stride) {
        float4 v = reinterpret_cast<const float4*>(in)[i];
        reinterpret_cast<__half2*>(out)[i * 2]     = __floats2half2_rn(v.x, v.y);
        reinterpret_cast<__half2*>(out)[i * 2 + 1] = __floats2half2_rn(v.z, v.w);
    }
}

// RMSNorm q,k over full C, fp16 in/out in place; q pre-scaled by 1/sqrt(D).
__global__ void rmsnorm_qk_h(__half* __restrict__ qkvh,
                             const float* __restrict__ qw, const float* __restrict__ kw)
{
    __half* row = qkvh + (size_t)blockIdx.x * (3 * C_DIM);
    int tid = threadIdx.x;
    const float scale = 0.088388347648318447f;   // 1/sqrt(128)
    float sq = 0.f, sk = 0.f;
    for (int i = tid * 8; i < C_DIM; i += 256 * 8) {
        float4 qr = *reinterpret_cast<const float4*>(row + i);           // 8 halfs
        float4 kr = *reinterpret_cast<const float4*>(row + C_DIM + i);
        const __half2* qh = reinterpret_cast<const __half2*>(&qr);
        const __half2* kh = reinterpret_cast<const __half2*>(&kr);
        #pragma unroll
        for (int j = 0; j < 4; j++) {
            float2 q2 = __half22float2(qh[j]);
            float2 k2 = __half22float2(kh[j]);
            sq += q2.x * q2.x + q2.y * q2.y;
            sk += k2.x * k2.x + k2.y * k2.y;
        }
    }
    #pragma unroll
    for (int o = 16; o; o >>= 1) {
        sq += __shfl_xor_sync(0xffffffffu, sq, o);
        sk += __shfl_xor_sync(0xffffffffu, sk, o);
    }
    __shared__ float s1[8], s2[8];
    int lane = tid & 31, warp = tid >> 5;
    if (lane == 0) { s1[warp] = sq; s2[warp] = sk; }
    __syncthreads();
    if (tid == 0) {
        float a = 0.f, b = 0.f;
        #pragma unroll
        for (int w = 0; w < 8; w++) { a += s1[w]; b += s2[w]; }
        s1[0] = rsqrtf(a / C_DIM + 1e-6f);
        s2[0] = rsqrtf(b / C_DIM + 1e-6f);
    }
    __syncthreads();
    float invq = s1[0] * scale, invk = s2[0];
    for (int i = tid * 8; i < C_DIM; i += 256 * 8) {
        float4 qr = *reinterpret_cast<const float4*>(row + i);
        float4 kr = *reinterpret_cast<const float4*>(row + C_DIM + i);
        __half2* qh = reinterpret_cast<__half2*>(&qr);
        __half2* kh = reinterpret_cast<__half2*>(&kr);
        float4 qo, ko;
        __half2* qoh = reinterpret_cast<__half2*>(&qo);
        __half2* koh = reinterpret_cast<__half2*>(&ko);
        #pragma unroll
        for (int j = 0; j < 4; j++) {
            float2 q2 = __half22float2(qh[j]);
            float2 k2 = __half22float2(kh[j]);
            qoh[j] = __floats2half2_rn(q2.x * invq * qw[i + j * 2], q2.y * invq * qw[i + j * 2 + 1]);
            koh[j] = __floats2half2_rn(k2.x * invk * kw[i + j * 2], k2.y * invk * kw[i + j * 2 + 1]);
        }
        *reinterpret_cast<float4*>(row + i) = qo;
        *reinterpret_cast<float4*>(row + C_DIM + i) = ko;
    }
}

extern "C" void kernel_launch(void* const* d_in, const int* in_sizes, int n_in,
                              void* d_out, int out_size)
{
    const float* x        = (const float*)d_in[0];
    const float* qkv_w    = (const float*)d_in[1];
    const float* qkv_b    = (const float*)d_in[2];
    const float* q_norm_w = (const float*)d_in[3];
    const float* k_norm_w = (const float*)d_in[4];
    const float* proj_w   = (const float*)d_in[5];
    const float* proj_b   = (const float*)d_in[6];
    float* out = (float*)d_out;

    __half *qkvh, *xh, *wqkvh, *wprojh, *atth;
    cudaGetSymbolAddress((void**)&qkvh,   g_qkvh);
    cudaGetSymbolAddress((void**)&xh,     g_xh);
    cudaGetSymbolAddress((void**)&wqkvh,  g_wqkvh);
    cudaGetSymbolAddress((void**)&wprojh, g_wprojh);
    cudaGetSymbolAddress((void**)&atth,   g_atth);

    cudaFuncSetAttribute(hgemm<__half>, cudaFuncAttributeMaxDynamicSharedMemorySize, HG_SMEM);
    cudaFuncSetAttribute(hgemm<float>,  cudaFuncAttributeMaxDynamicSharedMemorySize, HG_SMEM);
    cudaFuncSetAttribute(flash_attn_h, cudaFuncAttributeMaxDynamicSharedMemorySize, FAH_SMEM);

    dim3 blk(256);

    // 0. Convert GEMM operands to fp16
    conv_half<<<2048, 256>>>(x, xh, (long)M_ROWS * C_DIM / 4);
    conv_half<<<2048, 256>>>(qkv_w, wqkvh, (long)C_DIM * 3 * C_DIM / 4);
    conv_half<<<2048, 256>>>(proj_w, wprojh, (long)C_DIM * C_DIM / 4);

    // 1. QKV GEMM (fp16 in, fp16 out): [8200,3200] x [3200,9600] + bias
    {
        int TM = (M_ROWS + 127) / 128;          // 65
        int TN = (3 * C_DIM) / 128;             // 75
        hgemm<__half><<<dim3(TM * TN, 1, 1), blk, HG_SMEM>>>(
            xh, wqkvh, qkv_b, qkvh, M_ROWS, 3 * C_DIM, C_DIM,
            C_DIM, 3 * C_DIM, 3 * C_DIM, TM, TN);
    }

    // 2. RMSNorm q,k in place on fp16 (q pre-scaled)
    rmsnorm_qk_h<<<M_ROWS, blk>>>(qkvh, q_norm_w, k_norm_w);

    // 3-5. Fused flash attention (fp16) -> g_atth
    flash_attn_h<<<dim3(9, 200), blk, FAH_SMEM>>>(qkvh, atth);

    // 6. Proj GEMM (fp16 in, f32 out): [8200,3200] x [3200,3200] + bias -> out
    {
        int TM = (M_ROWS + 127) / 128;          // 65
        int TN = C_DIM / 128;                   // 25
        hgemm<float><<<dim3(TM * TN, 1, 1), blk, HG_SMEM>>>(
            atth, wprojh, proj_b, out, M_ROWS, C_DIM, C_DIM,
            C_DIM, C_DIM, C_DIM, TM, TN);
    }
}

// round 15
// speedup vs baseline: 5.7380x; 1.0183x over previous
#include <cuda_runtime.h>
#include <cuda_fp16.h>
#include <math.h>
#include <stdint.h>

// Problem constants
#define H_HEADS 25
#define B_DIM   8
#define N_TOK   1025
#define C_DIM   3200
#define D_HEAD  128
#define M_ROWS  (B_DIM * N_TOK)   // 8200

// Scratch (device globals)
__device__ __half g_qkvh[(size_t)M_ROWS * 3 * C_DIM];     // fp16 qkv (normed in place)
__device__ __half g_xh[(size_t)M_ROWS * C_DIM];           // x in fp16
__device__ __half g_wqkvh[(size_t)C_DIM * 3 * C_DIM];     // qkv_w in fp16
__device__ __half g_wprojh[(size_t)C_DIM * C_DIM];        // proj_w in fp16
__device__ __half g_atth[(size_t)M_ROWS * C_DIM];         // attention out in fp16

__device__ __forceinline__ void cp16(uint32_t dst, const void* src, int bytes) {
    asm volatile("cp.async.cg.shared.global [%0], [%1], 16, %2;\n"
                 :: "r"(dst), "l"(src), "r"(bytes));
}
__device__ __forceinline__ void cp16u(uint32_t dst, const void* src) {
    asm volatile("cp.async.cg.shared.global [%0], [%1], 16;\n"
                 :: "r"(dst), "l"(src));
}
__device__ __forceinline__ void cp_commit() { asm volatile("cp.async.commit_group;\n" ::); }
template<int NN>
__device__ __forceinline__ void cp_wait() { asm volatile("cp.async.wait_group %0;\n" :: "n"(NN)); }

__device__ __forceinline__ uint32_t smem_u32(const void* p) {
    return (uint32_t)__cvta_generic_to_shared(p);
}

__device__ __forceinline__ void mma_f16(float (&d)[4], const unsigned (&a)[4], const unsigned (&b)[2]) {
    asm volatile(
        "mma.sync.aligned.m16n8k16.row.col.f32.f16.f16.f32 "
        "{%0,%1,%2,%3}, {%4,%5,%6,%7}, {%8,%9}, {%0,%1,%2,%3};"
        : "+f"(d[0]), "+f"(d[1]), "+f"(d[2]), "+f"(d[3])
        : "r"(a[0]), "r"(a[1]), "r"(a[2]), "r"(a[3]), "r"(b[0]), "r"(b[1]));
}

__device__ __forceinline__ unsigned pack_h2(float a, float b) {
    __half2 h = __floats2half2_rn(a, b);
    return *reinterpret_cast<unsigned*>(&h);
}

#define LDSM_X4(r0, r1, r2, r3, addr) \
    asm volatile("ldmatrix.sync.aligned.m8n8.x4.shared.b16 {%0,%1,%2,%3}, [%4];" \
                 : "=r"(r0), "=r"(r1), "=r"(r2), "=r"(r3) : "r"(addr))
#define LDSM_X4_T(r0, r1, r2, r3, addr) \
    asm volatile("ldmatrix.sync.aligned.m8n8.x4.trans.shared.b16 {%0,%1,%2,%3}, [%4];" \
                 : "=r"(r0), "=r"(r1), "=r"(r2), "=r"(r3) : "r"(addr))

// =====================================================================
// FP16 GEMM, 128x128x64 CTA tile, 2 CTAs/SM, warp tile 64x32 (2x4 grid).
// 3-stage cp.async pipeline (wait 1). Double-buffered ldmatrix fragments.
// A smem: [128][72]h (144B rows); B smem: [64][136]h (272B rows).
// Requires: N % 128 == 0, K % 64 == 0.
// =====================================================================
#define HG_AB   (128 * 72 * 2)               // 18432 B
#define HG_BB   (64 * 136 * 2)               // 17408 B
#define HG_STB  (HG_AB + HG_BB)              // 35840 B
#define HG_SMEM (3 * HG_STB)                 // 107520 B

template<typename OutT>
__global__ void __launch_bounds__(256, 2)
hgemm(const __half* __restrict__ A, const __half* __restrict__ B,
      const float* __restrict__ bias, OutT* __restrict__ C,
      int M, int N, int K, long lda, long ldb, long ldc, int TM, int TN)
{
    extern __shared__ __half hsm[];

    int tm, tn;
    {
        const int GM = 16;
        int per = GM * TN;
        int g = blockIdx.x / per, r = blockIdx.x - g * per;
        int rows = TM - g * GM; if (rows > GM) rows = GM;
        tm = g * GM + r % rows;
        tn = r / rows;
    }
    const int bm0 = tm * 128;
    const int bn0 = tn * 128;

    const int tid = threadIdx.x;
    const int lane = tid & 31, warp = tid >> 5;
    const int wm = warp & 1, wn = warp >> 1;      // 2 x 4 warp grid
    const int lr = lane >> 2, lc = lane & 3;

    const uint32_t smbase = smem_u32(hsm);
    const int j8 = lane >> 3, i8 = lane & 7;
    const uint32_t a_lane = (uint32_t)((wm * 64 + (j8 & 1) * 8 + i8) * 144 + (j8 >> 1) * 16);
    const uint32_t b_lane = (uint32_t)(((j8 & 1) * 8 + i8) * 272 + (wn * 32 + (j8 >> 1) * 8) * 2);

    // ---- compact hoisted load state ----
    // A chunks: i-th chunk = base + i*32 rows.  c = tid&7 (256 % 8 == 0).
    const int arow0 = tid >> 3;            // 0..31
    const int ac = tid & 7;
    const __half* aP = A + (size_t)(bm0 + arow0) * lda + ac * 8;
    const uint32_t adst0 = (uint32_t)(arow0 * 144 + ac * 16);
    int abytes[4];
    #pragma unroll
    for (int i = 0; i < 4; i++)
        abytes[i] = (bm0 + arow0 + 32 * i < M) ? 16 : 0;
    const size_t alda32 = (size_t)32 * lda;
    // B chunks: i-th chunk = base + i*16 k-rows. nc = tid&15. Always in-range.
    const int bkr0 = tid >> 4;             // 0..15
    const int bnc = tid & 15;
    const __half* bP = B + (size_t)bkr0 * ldb + bn0 + bnc * 8;
    const uint32_t bdst0 = (uint32_t)(bkr0 * 272 + bnc * 16);
    const size_t bldb16 = (size_t)16 * ldb;
    const size_t bstep = (size_t)64 * ldb;

    float acc[4][4][4];
    #pragma unroll
    for (int mi = 0; mi < 4; mi++)
        #pragma unroll
        for (int ni = 0; ni < 4; ni++)
            #pragma unroll
            for (int r = 0; r < 4; r++)
                acc[mi][ni][r] = 0.f;

    const int T = K / 64;

    auto load_tiles = [&](int t, int s) {
        uint32_t sb = smbase + (uint32_t)s * HG_STB;
        const __half* ap = aP + (size_t)t * 64;
        #pragma unroll
        for (int i = 0; i < 4; i++)
            cp16(sb + adst0 + (uint32_t)(i * 32 * 144), ap + (size_t)i * alda32, abytes[i]);
        uint32_t sbb = sb + HG_AB;
        const __half* bp = bP + (size_t)t * bstep;
        #pragma unroll
        for (int i = 0; i < 4; i++)
            cp16u(sbb + bdst0 + (uint32_t)(i * 16 * 272), bp + (size_t)i * bldb16);
    };

    load_tiles(0, 0); cp_commit();
    if (T > 1) load_tiles(1, 1);
    cp_commit();

    unsigned af[2][4][4], bf[2][2][4];
    int scur = 0, snext = 2;
    for (int t = 0; t < T; t++) {
        if (t + 1 < T) cp_wait<1>(); else cp_wait<0>();
        __syncthreads();
        if (t + 2 < T) { load_tiles(t + 2, snext); }
        cp_commit();
        uint32_t abase = smbase + (uint32_t)scur * HG_STB + a_lane;
        uint32_t bbase = smbase + (uint32_t)scur * HG_STB + HG_AB + b_lane;
        if (++scur == 3) scur = 0;
        if (++snext == 3) snext = 0;

        // prologue: fragments for ks = 0
        #pragma unroll
        for (int mi = 0; mi < 4; mi++)
            LDSM_X4(af[0][mi][0], af[0][mi][1], af[0][mi][2], af[0][mi][3],
                    abase + (uint32_t)(mi * 2304));
        #pragma unroll
        for (int nb = 0; nb < 2; nb++)
            LDSM_X4_T(bf[0][nb][0], bf[0][nb][1], bf[0][nb][2], bf[0][nb][3],
                      bbase + (uint32_t)(nb * 32));

        #pragma unroll
        for (int ks = 0; ks < 4; ks++) {
            int cur = ks & 1, nxt = cur ^ 1;
            if (ks < 3) {
                #pragma unroll
                for (int mi = 0; mi < 4; mi++)
                    LDSM_X4(af[nxt][mi][0], af[nxt][mi][1], af[nxt][mi][2], af[nxt][mi][3],
                            abase + (uint32_t)(mi * 2304 + (ks + 1) * 32));
                #pragma unroll
                for (int nb = 0; nb < 2; nb++)
                    LDSM_X4_T(bf[nxt][nb][0], bf[nxt][nb][1], bf[nxt][nb][2], bf[nxt][nb][3],
                              bbase + (uint32_t)(nb * 32 + (ks + 1) * 4352));
            }
            #pragma unroll
            for (int mi = 0; mi < 4; mi++)
                #pragma unroll
                for (int nb = 0; nb < 2; nb++) {
                    unsigned b0[2] = { bf[cur][nb][0], bf[cur][nb][1] };
                    unsigned b1[2] = { bf[cur][nb][2], bf[cur][nb][3] };
                    mma_f16(acc[mi][nb * 2],     af[cur][mi], b0);
                    mma_f16(acc[mi][nb * 2 + 1], af[cur][mi], b1);
                }
        }
    }

    #pragma unroll
    for (int mi = 0; mi < 4; mi++) {
        #pragma unroll
        for (int ni = 0; ni < 4; ni++) {
            int r0 = bm0 + wm * 64 + mi * 16 + lr;
            int c0 = bn0 + wn * 32 + ni * 8 + lc * 2;
            float b0 = 0.f, b1 = 0.f;
            if (bias) { b0 = bias[c0]; b1 = bias[c0 + 1]; }
            #pragma unroll
            for (int rr = 0; rr < 2; rr++) {
                int rw = r0 + rr * 8;
                if (rw < M) {
                    float v0 = acc[mi][ni][rr * 2]     + b0;
                    float v1 = acc[mi][ni][rr * 2 + 1] + b1;
                    if constexpr (sizeof(OutT) == 2) {
                        *reinterpret_cast<__half2*>(
                            reinterpret_cast<__half*>(C) + (size_t)rw * ldc + c0) =
                            __floats2half2_rn(v0, v1);
                    } else {
                        reinterpret_cast<float*>(C)[(size_t)rw * ldc + c0]     = v0;
                        reinterpret_cast<float*>(C)[(size_t)rw * ldc + c0 + 1] = v1;
                    }
                }
            }
        }
    }
}

// =====================================================================
// Fused flash attention, full fp16 datapath; hoisted KV load pointers.
// (unchanged from R14)
// =====================================================================
#define FAH_QB   (128 * 136 * 2)
#define FAH_KVB  (64 * 136 * 2)
#define FAH_SMEM (FAH_QB + 4 * FAH_KVB + 1024)
#define FA_T     17

__global__ void __launch_bounds__(256, 1)
flash_attn_h(const __half* __restrict__ qkvh, __half* __restrict__ Og)
{
    extern __shared__ char fsm[];
    const uint32_t smb = smem_u32(fsm);
    const int tid = threadIdx.x, w = tid >> 5, lane = tid & 31;
    const int wr = w >> 1, wc = w & 1;
    const int lr = lane >> 2, lc = lane & 3;
    const int j8 = lane >> 3, i8 = lane & 7;
    const int qt = blockIdx.x, bh = blockIdx.y;
    const int b = bh / H_HEADS, h = bh - b * H_HEADS;

    const __half* qbase = qkvh + (size_t)b * N_TOK * (3 * C_DIM) + h * D_HEAD;

    const uint32_t qa_lane = (uint32_t)((wr * 32 + (j8 & 1) * 8 + i8) * 272 + (j8 >> 1) * 16);
    const uint32_t kb_lane = (uint32_t)((wc * 32 + (j8 & 1) * 8 + i8) * 272 + (j8 >> 1) * 16);
    const uint32_t vb_lane = (uint32_t)(((wc * 32 + (j8 & 1) * 8 + i8) * 272) + ((j8 >> 1) * 8) * 2);

    #pragma unroll
    for (int i = 0; i < 8; i++) {
        int id = tid + i * 256;
        int r = id >> 4, c = id & 15;
        int q = qt * 128 + r;
        const __half* src = qbase; int bytes = 0;
        if (q < N_TOK) { src = qbase + (size_t)q * (3 * C_DIM) + c * 8; bytes = 16; }
        cp16(smb + (uint32_t)(r * 272 + c * 16), src, bytes);
    }

    int kv_r[4];
    const __half* kv_ksrc[4];
    const __half* kv_vsrc[4];
    uint32_t kv_dst[4];
    #pragma unroll
    for (int i = 0; i < 4; i++) {
        int id = tid + i * 256;
        int r = id >> 4, c = id & 15;
        kv_r[i] = r;
        kv_ksrc[i] = qbase + (size_t)r * (3 * C_DIM) + C_DIM + c * 8;
        kv_vsrc[i] = kv_ksrc[i] + C_DIM;
        kv_dst[i] = (uint32_t)(r * 272 + c * 16);
    }
    const long kvstep = (long)64 * (3 * C_DIM);

    auto load_kv = [&](int t, int s) {
        uint32_t kb = smb + FAH_QB + (uint32_t)s * 2 * FAH_KVB;
        uint32_t vb = kb + FAH_KVB;
        long off = (long)t * kvstep;
        int base = t * 64;
        #pragma unroll
        for (int i = 0; i < 4; i++) {
            int bytes = (base + kv_r[i] < N_TOK) ? 16 : 0;
            cp16(kb + kv_dst[i], kv_ksrc[i] + off, bytes);
            cp16(vb + kv_dst[i], kv_vsrc[i] + off, bytes);
        }
    };
    load_kv(0, 0);
    cp_commit();

    float o[2][16][4];
    #pragma unroll
    for (int mi = 0; mi < 2; mi++)
        #pragma unroll
        for (int ni = 0; ni < 16; ni++)
            #pragma unroll
            for (int r = 0; r < 4; r++) o[mi][ni][r] = 0.f;
    float mrow[4] = {-1e30f, -1e30f, -1e30f, -1e30f};
    float lrow[4] = {0.f, 0.f, 0.f, 0.f};

    for (int t = 0; t < FA_T; t++) {
        int s = t & 1;
        cp_wait<0>();
        __syncthreads();
        if (t + 1 < FA_T) load_kv(t + 1, s ^ 1);
        cp_commit();

        uint32_t kb = smb + FAH_QB + (uint32_t)s * 2 * FAH_KVB;
        uint32_t vb = kb + FAH_KVB;

        float sa[2][4][4];
        #pragma unroll
        for (int mi = 0; mi < 2; mi++)
            #pragma unroll
            for (int ni = 0; ni < 4; ni++)
                #pragma unroll
                for (int r = 0; r < 4; r++) sa[mi][ni][r] = 0.f;

        uint32_t qb0 = smb + qa_lane;
        uint32_t kb0 = kb + kb_lane;
        #pragma unroll
        for (int ks = 0; ks < 8; ks++) {
            unsigned af[2][4], kf[2][4];
            #pragma unroll
            for (int mi = 0; mi < 2; mi++)
                LDSM_X4(af[mi][0], af[mi][1], af[mi][2], af[mi][3],
                        qb0 + (uint32_t)(mi * 16 * 272 + ks * 32));
            #pragma unroll
            for (int g = 0; g < 2; g++)
                LDSM_X4(kf[g][0], kf[g][1], kf[g][2], kf[g][3],
                        kb0 + (uint32_t)(g * 16 * 272 + ks * 32));
            #pragma unroll
            for (int mi = 0; mi < 2; mi++)
                #pragma unroll
                for (int g = 0; g < 2; g++) {
                    unsigned b0[2] = { kf[g][0], kf[g][2] };
                    unsigned b1[2] = { kf[g][1], kf[g][3] };
                    mma_f16(sa[mi][g * 2],     af[mi], b0);
                    mma_f16(sa[mi][g * 2 + 1], af[mi], b1);
                }
        }

        if (t == FA_T - 1) {
            #pragma unroll
            for (int ni = 0; ni < 4; ni++) {
                int col = t * 64 + wc * 32 + ni * 8 + 2 * lc;
                if (col >= N_TOK) {
                    #pragma unroll
                    for (int mi = 0; mi < 2; mi++) { sa[mi][ni][0] = -1e30f; sa[mi][ni][2] = -1e30f; }
                }
                if (col + 1 >= N_TOK) {
                    #pragma unroll
                    for (int mi = 0; mi < 2; mi++) { sa[mi][ni][1] = -1e30f; sa[mi][ni][3] = -1e30f; }
                }
            }
        }

        float tm[4] = {-1e30f, -1e30f, -1e30f, -1e30f};
        #pragma unroll
        for (int mi = 0; mi < 2; mi++)
            #pragma unroll
            for (int ni = 0; ni < 4; ni++) {
                tm[mi * 2 + 0] = fmaxf(tm[mi * 2 + 0], fmaxf(sa[mi][ni][0], sa[mi][ni][1]));
                tm[mi * 2 + 1] = fmaxf(tm[mi * 2 + 1], fmaxf(sa[mi][ni][2], sa[mi][ni][3]));
            }
        #pragma unroll
        for (int j = 0; j < 4; j++) {
            tm[j] = fmaxf(tm[j], __shfl_xor_sync(0xffffffffu, tm[j], 1));
            tm[j] = fmaxf(tm[j], __shfl_xor_sync(0xffffffffu, tm[j], 2));
        }
        float fj[4];
        #pragma unroll
        for (int j = 0; j < 4; j++) {
            float mn = fmaxf(mrow[j], tm[j]);
            fj[j] = __expf(mrow[j] - mn);
            mrow[j] = mn;
        }
        float rs[4] = {0.f, 0.f, 0.f, 0.f};
        #pragma unroll
        for (int mi = 0; mi < 2; mi++)
            #pragma unroll
            for (int ni = 0; ni < 4; ni++) {
                sa[mi][ni][0] = __expf(sa[mi][ni][0] - mrow[mi * 2]);     rs[mi * 2] += sa[mi][ni][0];
                sa[mi][ni][1] = __expf(sa[mi][ni][1] - mrow[mi * 2]);     rs[mi * 2] += sa[mi][ni][1];
                sa[mi][ni][2] = __expf(sa[mi][ni][2] - mrow[mi * 2 + 1]); rs[mi * 2 + 1] += sa[mi][ni][2];
                sa[mi][ni][3] = __expf(sa[mi][ni][3] - mrow[mi * 2 + 1]); rs[mi * 2 + 1] += sa[mi][ni][3];
            }
        #pragma unroll
        for (int j = 0; j < 4; j++) {
            rs[j] += __shfl_xor_sync(0xffffffffu, rs[j], 1);
            rs[j] += __shfl_xor_sync(0xffffffffu, rs[j], 2);
            lrow[j] = lrow[j] * fj[j] + rs[j];
        }
        #pragma unroll
        for (int mi = 0; mi < 2; mi++)
            #pragma unroll
            for (int ni = 0; ni < 16; ni++) {
                o[mi][ni][0] *= fj[mi * 2];     o[mi][ni][1] *= fj[mi * 2];
                o[mi][ni][2] *= fj[mi * 2 + 1]; o[mi][ni][3] *= fj[mi * 2 + 1];
            }

        uint32_t vb0 = vb + vb_lane;
        #pragma unroll
        for (int ks2 = 0; ks2 < 2; ks2++) {
            unsigned a[2][4];
            #pragma unroll
            for (int mi = 0; mi < 2; mi++) {
                a[mi][0] = pack_h2(sa[mi][2 * ks2][0],     sa[mi][2 * ks2][1]);
                a[mi][1] = pack_h2(sa[mi][2 * ks2][2],     sa[mi][2 * ks2][3]);
                a[mi][2] = pack_h2(sa[mi][2 * ks2 + 1][0], sa[mi][2 * ks2 + 1][1]);
                a[mi][3] = pack_h2(sa[mi][2 * ks2 + 1][2], sa[mi][2 * ks2 + 1][3]);
            }
            #pragma unroll
            for (int nb = 0; nb < 8; nb++) {
                unsigned vf[4];
                LDSM_X4_T(vf[0], vf[1], vf[2], vf[3],
                          vb0 + (uint32_t)(ks2 * 16 * 272 + nb * 32));
                unsigned b0[2] = { vf[0], vf[1] };
                unsigned b1[2] = { vf[2], vf[3] };
                #pragma unroll
                for (int mi = 0; mi < 2; mi++) {
                    mma_f16(o[mi][nb * 2],     a[mi], b0);
                    mma_f16(o[mi][nb * 2 + 1], a[mi], b1);
                }
            }
        }
    }

    float* Ms = reinterpret_cast<float*>(fsm + FAH_QB);
    float* stats = reinterpret_cast<float*>(fsm + FAH_QB + 128 * 132 * 4);
    __syncthreads();
    if (wc == 1) {
        #pragma unroll
        for (int mi = 0; mi < 2; mi++) {
            int r0 = wr * 32 + mi * 16 + lr;
            #pragma unroll
            for (int ni = 0; ni < 16; ni++) {
                *reinterpret_cast<float2*>(&Ms[r0 * 132 + ni * 8 + 2 * lc]) =
                    make_float2(o[mi][ni][0], o[mi][ni][1]);
                *reinterpret_cast<float2*>(&Ms[(r0 + 8) * 132 + ni * 8 + 2 * lc]) =
                    make_float2(o[mi][ni][2], o[mi][ni][3]);
            }
            if (lc == 0) {
                stats[r0 * 2]           = mrow[mi * 2];
                stats[r0 * 2 + 1]       = lrow[mi * 2];
                stats[(r0 + 8) * 2]     = mrow[mi * 2 + 1];
                stats[(r0 + 8) * 2 + 1] = lrow[mi * 2 + 1];
            }
        }
    }
    __syncthreads();
    if (wc == 0) {
        #pragma unroll
        for (int mi = 0; mi < 2; mi++) {
            #pragma unroll
            for (int half = 0; half < 2; half++) {
                int r0 = wr * 32 + mi * 16 + lr + half * 8;
                int j = mi * 2 + half;
                float m1 = stats[r0 * 2];
                float l1 = stats[r0 * 2 + 1];
                float mm = fmaxf(mrow[j], m1);
                float f0 = __expf(mrow[j] - mm), f1 = __expf(m1 - mm);
                float ll = lrow[j] * f0 + l1 * f1;
                float inv = 1.f / ll;
                int rg = qt * 128 + r0;
                if (rg < N_TOK) {
                    __half* dst = Og + ((size_t)(b * N_TOK + rg)) * C_DIM + h * D_HEAD;
                    #pragma unroll
                    for (int ni = 0; ni < 16; ni++) {
                        float2 o1 = *reinterpret_cast<float2*>(&Ms[r0 * 132 + ni * 8 + 2 * lc]);
                        float v0 = (o[mi][ni][half * 2]     * f0 + o1.x * f1) * inv;
                        float v1 = (o[mi][ni][half * 2 + 1] * f0 + o1.y * f1) * inv;
                        *reinterpret_cast<__half2*>(&dst[ni * 8 + 2 * lc]) =
                            __floats2half2_rn(v0, v1);
                    }
                }
            }
        }
    }
}

// ===================== pre-processing kernels =====================

__global__ void conv_half(const float* __restrict__ in, __half* __restrict__ out, long n4)
{
    long i = (long)blockIdx.x * blockDim.x + threadIdx.x;
    long stride = (long)gridDim.x * blockDim.x;
    for (; i < n4; i += stride) {
        float4 v = reinterpret_cast<const float4*>(in)[i];
        reinterpret_cast<__half2*>(out)[i * 2]     = __floats2half2_rn(v.x, v.y);
        reinterpret_cast<__half2*>(out)[i * 2 + 1] = __floats2half2_rn(v.z, v.w);
    }
}

// RMSNorm q,k over full C, fp16 in/out in place; q pre-scaled by 1/sqrt(D).
__global__ void rmsnorm_qk_h(__half* __restrict__ qkvh,
                             const float* __restrict__ qw, const float* __restrict__ kw)
{
    __half* row = qkvh + (size_t)blockIdx.x * (3 * C_DIM);
    int tid = threadIdx.x;
    const float scale = 0.088388347648318447f;   // 1/sqrt(128)
    float sq = 0.f, sk = 0.f;
    for (int i = tid * 8; i < C_DIM; i += 256 * 8) {
        float4 qr = *reinterpret_cast<const float4*>(row + i);           // 8 halfs
        float4 kr = *reinterpret_cast<const float4*>(row + C_DIM + i);
        const __half2* qh = reinterpret_cast<const __half2*>(&qr);
        const __half2* kh = reinterpret_cast<const __half2*>(&kr);
        #pragma unroll
        for (int j = 0; j < 4; j++) {
            float2 q2 = __half22float2(qh[j]);
            float2 k2 = __half22float2(kh[j]);
            sq += q2.x * q2.x + q2.y * q2.y;
            sk += k2.x * k2.x + k2.y * k2.y;
        }
    }
    #pragma unroll
    for (int o = 16; o; o >>= 1) {
        sq += __shfl_xor_sync(0xffffffffu, sq, o);
        sk += __shfl_xor_sync(0xffffffffu, sk, o);
    }
    __shared__ float s1[8], s2[8];
    int lane = tid & 31, warp = tid >> 5;
    if (lane == 0) { s1[warp] = sq; s2[warp] = sk; }
    __syncthreads();
    if (tid == 0) {
        float a = 0.f, b = 0.f;
        #pragma unroll
        for (int w = 0; w < 8; w++) { a += s1[w]; b += s2[w]; }
        s1[0] = rsqrtf(a / C_DIM + 1e-6f);
        s2[0] = rsqrtf(b / C_DIM + 1e-6f);
    }
    __syncthreads();
    float invq = s1[0] * scale, invk = s2[0];
    for (int i = tid * 8; i < C_DIM; i += 256 * 8) {
        float4 qr = *reinterpret_cast<const float4*>(row + i);
        float4 kr = *reinterpret_cast<const float4*>(row + C_DIM + i);
        __half2* qh = reinterpret_cast<__half2*>(&qr);
        __half2* kh = reinterpret_cast<__half2*>(&kr);
        float4 qo, ko;
        __half2* qoh = reinterpret_cast<__half2*>(&qo);
        __half2* koh = reinterpret_cast<__half2*>(&ko);
        #pragma unroll
        for (int j = 0; j < 4; j++) {
            float2 q2 = __half22float2(qh[j]);
            float2 k2 = __half22float2(kh[j]);
            qoh[j] = __floats2half2_rn(q2.x * invq * qw[i + j * 2], q2.y * invq * qw[i + j * 2 + 1]);
            koh[j] = __floats2half2_rn(k2.x * invk * kw[i + j * 2], k2.y * invk * kw[i + j * 2 + 1]);
        }
        *reinterpret_cast<float4*>(row + i) = qo;
        *reinterpret_cast<float4*>(row + C_DIM + i) = ko;
    }
}

extern "C" void kernel_launch(void* const* d_in, const int* in_sizes, int n_in,
                              void* d_out, int out_size)
{
    const float* x        = (const float*)d_in[0];
    const float* qkv_w    = (const float*)d_in[1];
    const float* qkv_b    = (const float*)d_in[2];
    const float* q_norm_w = (const float*)d_in[3];
    const float* k_norm_w = (const float*)d_in[4];
    const float* proj_w   = (const float*)d_in[5];
    const float* proj_b   = (const float*)d_in[6];
    float* out = (float*)d_out;

    __half *qkvh, *xh, *wqkvh, *wprojh, *atth;
    cudaGetSymbolAddress((void**)&qkvh,   g_qkvh);
    cudaGetSymbolAddress((void**)&xh,     g_xh);
    cudaGetSymbolAddress((void**)&wqkvh,  g_wqkvh);
    cudaGetSymbolAddress((void**)&wprojh, g_wprojh);
    cudaGetSymbolAddress((void**)&atth,   g_atth);

    cudaFuncSetAttribute(hgemm<__half>, cudaFuncAttributeMaxDynamicSharedMemorySize, HG_SMEM);
    cudaFuncSetAttribute(hgemm<float>,  cudaFuncAttributeMaxDynamicSharedMemorySize, HG_SMEM);
    cudaFuncSetAttribute(flash_attn_h, cudaFuncAttributeMaxDynamicSharedMemorySize, FAH_SMEM);

    dim3 blk(256);

    // 0. Convert GEMM operands to fp16
    conv_half<<<2048, 256>>>(x, xh, (long)M_ROWS * C_DIM / 4);
    conv_half<<<2048, 256>>>(qkv_w, wqkvh, (long)C_DIM * 3 * C_DIM / 4);
    conv_half<<<2048, 256>>>(proj_w, wprojh, (long)C_DIM * C_DIM / 4);

    // 1. QKV GEMM (fp16 in, fp16 out): [8200,3200] x [3200,9600] + bias
    {
        int TM = (M_ROWS + 127) / 128;          // 65
        int TN = (3 * C_DIM) / 128;             // 75
        hgemm<__half><<<dim3(TM * TN, 1, 1), blk, HG_SMEM>>>(
            xh, wqkvh, qkv_b, qkvh, M_ROWS, 3 * C_DIM, C_DIM,
            C_DIM, 3 * C_DIM, 3 * C_DIM, TM, TN);
    }

    // 2. RMSNorm q,k in place on fp16 (q pre-scaled)
    rmsnorm_qk_h<<<M_ROWS, blk>>>(qkvh, q_norm_w, k_norm_w);

    // 3-5. Fused flash attention (fp16) -> g_atth
    flash_attn_h<<<dim3(9, 200), blk, FAH_SMEM>>>(qkvh, atth);

    // 6. Proj GEMM (fp16 in, f32 out): [8200,3200] x [3200,3200] + bias -> out
    {
        int TM = (M_ROWS + 127) / 128;          // 65
        int TN = C_DIM / 128;                   // 25
        hgemm<float><<<dim3(TM * TN, 1, 1), blk, HG_SMEM>>>(
            atth, wprojh, proj_b, out, M_ROWS, C_DIM, C_DIM,
            C_DIM, C_DIM, C_DIM, TM, TN);
    }
}